// round 4
// baseline (speedup 1.0000x reference)
#include <cuda_runtime.h>
#include <math.h>

#define EMBED 512
#define NH    8
#define DH    64
#define BATCH 2
#define SEQ   2048
#define ROWS  (BATCH*SEQ)   // 4096
#define FF    2048

// ---------------- scratch (no allocation allowed) ----------------
__device__ float g_q[ROWS*EMBED];
__device__ float g_k[ROWS*EMBED];
__device__ float g_v[ROWS*EMBED];
__device__ float g_attn[ROWS*EMBED];
__device__ float g_x[ROWS*EMBED];
__device__ float g_h[ROWS*FF];

// ---------------- GEMM: C[M,N] = A[M,K] @ B[K,N] + bias (+epilogue) ----------
#define BM 128
#define BN 128
#define BK 8
#define TM 8
#define TN 8

#define EP_BIAS 0
#define EP_RES  1
#define EP_GELU 2

__device__ __forceinline__ void sgemm_body(
    const float* __restrict__ A, const float* __restrict__ B,
    const float* __restrict__ bias, const float* __restrict__ R,
    float* __restrict__ C, int M, int N, int K, int ep,
    int bm, int bn)
{
    __shared__ float As[BK][BM];
    __shared__ float Bs[BK][BN];
    const int tid = threadIdx.x;

    const int aRow = tid >> 1;          // 0..127
    const int aCol = (tid & 1) * 4;     // 0 or 4
    const int bRow = tid >> 5;          // 0..7
    const int bCol = (tid & 31) * 4;    // 0..124

    const int tr = (tid >> 4) * TM;
    const int tc = (tid & 15) * TN;

    float acc[TM][TN];
    #pragma unroll
    for (int i = 0; i < TM; i++)
        #pragma unroll
        for (int j = 0; j < TN; j++) acc[i][j] = 0.f;

    // prologue: tile 0 -> smem
    {
        float4 a4 = *(const float4*)(A + (size_t)(bm + aRow) * K + aCol);
        As[aCol + 0][aRow] = a4.x; As[aCol + 1][aRow] = a4.y;
        As[aCol + 2][aRow] = a4.z; As[aCol + 3][aRow] = a4.w;
        *(float4*)(&Bs[bRow][bCol]) = *(const float4*)(B + (size_t)bRow * N + bn + bCol);
    }
    __syncthreads();

    const int nk = K / BK;
    for (int it = 0; it < nk; it++) {
        float4 a_pf, b_pf;
        const bool more = (it + 1 < nk);
        if (more) {
            const int k0 = (it + 1) * BK;
            a_pf = *(const float4*)(A + (size_t)(bm + aRow) * K + k0 + aCol);
            b_pf = *(const float4*)(B + (size_t)(k0 + bRow) * N + bn + bCol);
        }

        #pragma unroll
        for (int kk = 0; kk < BK; kk++) {
            float ra[TM], rb[TN];
            #pragma unroll
            for (int i = 0; i < TM; i++) ra[i] = As[kk][tr + i];
            #pragma unroll
            for (int j = 0; j < TN; j++) rb[j] = Bs[kk][tc + j];
            #pragma unroll
            for (int i = 0; i < TM; i++)
                #pragma unroll
                for (int j = 0; j < TN; j++) acc[i][j] += ra[i] * rb[j];
        }
        __syncthreads();
        if (more) {
            As[aCol + 0][aRow] = a_pf.x; As[aCol + 1][aRow] = a_pf.y;
            As[aCol + 2][aRow] = a_pf.z; As[aCol + 3][aRow] = a_pf.w;
            *(float4*)(&Bs[bRow][bCol]) = b_pf;
            __syncthreads();
        }
    }

    #pragma unroll
    for (int i = 0; i < TM; i++) {
        const int m = bm + tr + i;
        #pragma unroll
        for (int j = 0; j < TN; j++) {
            const int n = bn + tc + j;
            float v = acc[i][j] + bias[n];
            if (ep == EP_RES)       v += R[(size_t)m * N + n];
            else if (ep == EP_GELU) v = 0.5f * v * (1.0f + erff(v * 0.70710678118654752f));
            C[(size_t)m * N + n] = v;
        }
    }
}

__global__ __launch_bounds__(256) void sgemm_ep(
    const float* __restrict__ A, const float* __restrict__ B,
    const float* __restrict__ bias, const float* __restrict__ R,
    float* __restrict__ C, int M, int N, int K, int ep)
{
    sgemm_body(A, B, bias, R, C, M, N, K, ep,
               blockIdx.y * BM, blockIdx.x * BN);
}

// one launch for Q/K/V projections: blockIdx.z selects the GEMM
__global__ __launch_bounds__(256) void sgemm_qkv(
    const float* __restrict__ Aq, const float* __restrict__ Akv,
    const float* __restrict__ Wq, const float* __restrict__ bq,
    const float* __restrict__ Wk, const float* __restrict__ bk,
    const float* __restrict__ Wv, const float* __restrict__ bv,
    float* __restrict__ Cq, float* __restrict__ Ck, float* __restrict__ Cv)
{
    const int z = blockIdx.z;
    const float* A = (z == 0) ? Aq : Akv;
    const float* W = (z == 0) ? Wq : (z == 1) ? Wk : Wv;
    const float* bia = (z == 0) ? bq : (z == 1) ? bk : bv;
    float* C = (z == 0) ? Cq : (z == 1) ? Ck : Cv;
    sgemm_body(A, W, bia, nullptr, C, ROWS, EMBED, EMBED, EP_BIAS,
               blockIdx.y * BM, blockIdx.x * BN);
}

// ---------------- flash attention: 4 threads per query, 16 dims each --------
#define ATQ 64
#define ATK 32

__global__ __launch_bounds__(256) void flash_attn2(
    const float* __restrict__ Q, const float* __restrict__ Km,
    const float* __restrict__ V, float* __restrict__ O, int causal)
{
    __shared__ float sk[ATK][DH];   // 8 KB
    __shared__ float sv[ATK][DH];   // 8 KB
    const int b = blockIdx.z, h = blockIdx.y, qt = blockIdx.x;
    const int t = threadIdx.x;
    const int qi = qt * ATQ + (t >> 2);   // query index
    const int sl = t & 3;                 // dim slice: sl*16 .. sl*16+15
    const size_t qoff = ((size_t)(b * SEQ + qi)) * EMBED + h * DH + sl * 16;

    float4 qv[4];
    #pragma unroll
    for (int i = 0; i < 4; i++) {
        float4 x = *(const float4*)(Q + qoff + 4 * i);
        x.x *= 0.125f; x.y *= 0.125f; x.z *= 0.125f; x.w *= 0.125f; // 1/sqrt(64)
        qv[i] = x;
    }
    float4 acc[4];
    #pragma unroll
    for (int i = 0; i < 4; i++) acc[i] = make_float4(0.f, 0.f, 0.f, 0.f);
    float s_loc[ATK / 4];
    float mi = -1e30f, li = 0.f;

    const int nkt = causal ? (qt * ATQ + ATQ) / ATK : SEQ / ATK;
    for (int kt = 0; kt < nkt; kt++) {
        // cooperative tile load: 512 float4 per array, 2 per thread
        #pragma unroll
        for (int i = 0; i < 2; i++) {
            const int idx = t + i * 256;
            const int r = idx >> 4;
            const int c = (idx & 15) * 4;
            const size_t goff = ((size_t)(b * SEQ + kt * ATK + r)) * EMBED + h * DH + c;
            *(float4*)(&sk[r][c]) = *(const float4*)(Km + goff);
            *(float4*)(&sv[r][c]) = *(const float4*)(V  + goff);
        }
        __syncthreads();

        // score phase: partial dots + butterfly reduce within 4-thread group
        float tmax = -1e30f;
        #pragma unroll
        for (int j = 0; j < ATK; j++) {
            float d = 0.f;
            #pragma unroll
            for (int i = 0; i < 4; i++) {
                float4 kv = *(const float4*)(&sk[j][sl * 16 + 4 * i]);
                d += qv[i].x * kv.x + qv[i].y * kv.y + qv[i].z * kv.z + qv[i].w * kv.w;
            }
            d += __shfl_xor_sync(0xffffffffu, d, 1);
            d += __shfl_xor_sync(0xffffffffu, d, 2);
            if (causal && (kt * ATK + j) > qi) d = -1e30f;
            if ((j & 3) == sl) s_loc[j >> 2] = d;
            tmax = fmaxf(tmax, d);
        }

        const float mnew = fmaxf(mi, tmax);
        const float corr = __expf(mi - mnew);
        li *= corr;
        #pragma unroll
        for (int i = 0; i < 4; i++) {
            acc[i].x *= corr; acc[i].y *= corr; acc[i].z *= corr; acc[i].w *= corr;
        }

        // PV phase: owner computes exp once, width-4 shuffle broadcast
        #pragma unroll
        for (int jg = 0; jg < ATK / 4; jg++) {
            const float e = __expf(s_loc[jg] - mnew);
            #pragma unroll
            for (int o = 0; o < 4; o++) {
                const float p = __shfl_sync(0xffffffffu, e, o, 4);
                const int j = jg * 4 + o;
                li += p;
                #pragma unroll
                for (int i = 0; i < 4; i++) {
                    float4 vv = *(const float4*)(&sv[j][sl * 16 + 4 * i]);
                    acc[i].x += p * vv.x; acc[i].y += p * vv.y;
                    acc[i].z += p * vv.z; acc[i].w += p * vv.w;
                }
            }
        }
        mi = mnew;
        __syncthreads();
    }

    const float inv = 1.f / li;
    #pragma unroll
    for (int i = 0; i < 4; i++) {
        float4 o = acc[i];
        o.x *= inv; o.y *= inv; o.z *= inv; o.w *= inv;
        *(float4*)(O + qoff + 4 * i) = o;
    }
}

// ---------------- LayerNorm over last dim (512) -----------------------------
__global__ __launch_bounds__(128) void layernorm_k(
    const float* __restrict__ X, const float* __restrict__ G,
    const float* __restrict__ Bt, float* __restrict__ Y)
{
    const int row = blockIdx.x;
    const int t = threadIdx.x;
    const float* xr = X + (size_t)row * EMBED;
    float4 v = *(const float4*)(xr + t * 4);
    float s  = v.x + v.y + v.z + v.w;
    float ss = v.x * v.x + v.y * v.y + v.z * v.z + v.w * v.w;
    #pragma unroll
    for (int o = 16; o > 0; o >>= 1) {
        s  += __shfl_xor_sync(0xffffffffu, s,  o);
        ss += __shfl_xor_sync(0xffffffffu, ss, o);
    }
    __shared__ float sh_s[4], sh_ss[4];
    const int w = t >> 5;
    if ((t & 31) == 0) { sh_s[w] = s; sh_ss[w] = ss; }
    __syncthreads();
    s  = sh_s[0] + sh_s[1] + sh_s[2] + sh_s[3];
    ss = sh_ss[0] + sh_ss[1] + sh_ss[2] + sh_ss[3];
    const float mean = s * (1.f / EMBED);
    const float var  = ss * (1.f / EMBED) - mean * mean;
    const float rstd = rsqrtf(var + 1e-5f);
    float4 gg = *(const float4*)(G  + t * 4);
    float4 bb = *(const float4*)(Bt + t * 4);
    float4 o;
    o.x = (v.x - mean) * rstd * gg.x + bb.x;
    o.y = (v.y - mean) * rstd * gg.y + bb.y;
    o.z = (v.z - mean) * rstd * gg.z + bb.z;
    o.w = (v.w - mean) * rstd * gg.w + bb.w;
    *(float4*)(Y + (size_t)row * EMBED + t * 4) = o;
}

// ---------------- launch --------------------------------------------------
extern "C" void kernel_launch(void* const* d_in, const int* in_sizes, int n_in,
                              void* d_out, int out_size)
{
    const float* x     = (const float*)d_in[0];
    const float* enc   = (const float*)d_in[1];
    const float* sa_wq = (const float*)d_in[2];
    const float* sa_bq = (const float*)d_in[3];
    const float* sa_wk = (const float*)d_in[4];
    const float* sa_bk = (const float*)d_in[5];
    const float* sa_wv = (const float*)d_in[6];
    const float* sa_bv = (const float*)d_in[7];
    const float* sa_wo = (const float*)d_in[8];
    const float* sa_bo = (const float*)d_in[9];
    const float* ca_wq = (const float*)d_in[10];
    const float* ca_bq = (const float*)d_in[11];
    const float* ca_wk = (const float*)d_in[12];
    const float* ca_bk = (const float*)d_in[13];
    const float* ca_wv = (const float*)d_in[14];
    const float* ca_bv = (const float*)d_in[15];
    const float* ca_wo = (const float*)d_in[16];
    const float* ca_bo = (const float*)d_in[17];
    const float* ln1_g = (const float*)d_in[18];
    const float* ln1_b = (const float*)d_in[19];
    const float* ln2_g = (const float*)d_in[20];
    const float* ln2_b = (const float*)d_in[21];
    const float* ln3_g = (const float*)d_in[22];
    const float* ln3_b = (const float*)d_in[23];
    const float* ff_w1 = (const float*)d_in[24];
    const float* ff_b1 = (const float*)d_in[25];
    const float* ff_w2 = (const float*)d_in[26];
    const float* ff_b2 = (const float*)d_in[27];
    float* out = (float*)d_out;

    float *q, *k, *v, *attn, *xb, *hb;
    cudaGetSymbolAddress((void**)&q,    g_q);
    cudaGetSymbolAddress((void**)&k,    g_k);
    cudaGetSymbolAddress((void**)&v,    g_v);
    cudaGetSymbolAddress((void**)&attn, g_attn);
    cudaGetSymbolAddress((void**)&xb,   g_x);
    cudaGetSymbolAddress((void**)&hb,   g_h);

    dim3 g512(EMBED / BN, ROWS / BM);        // (4, 32)
    dim3 gqkv(EMBED / BN, ROWS / BM, 3);     // (4, 32, 3)
    dim3 gff (FF    / BN, ROWS / BM);        // (16, 32)
    dim3 gfl (SEQ / ATQ, NH, BATCH);         // (32, 8, 2)

    // ---- self attention (causal) ----
    sgemm_qkv<<<gqkv, 256>>>(x, x, sa_wq, sa_bq, sa_wk, sa_bk, sa_wv, sa_bv, q, k, v);
    flash_attn2<<<gfl, 256>>>(q, k, v, attn, 1);
    sgemm_ep<<<g512, 256>>>(attn, sa_wo, sa_bo, x, xb, ROWS, EMBED, EMBED, EP_RES);
    layernorm_k<<<ROWS, 128>>>(xb, ln1_g, ln1_b, xb);

    // ---- cross attention ----
    sgemm_qkv<<<gqkv, 256>>>(xb, enc, ca_wq, ca_bq, ca_wk, ca_bk, ca_wv, ca_bv, q, k, v);
    flash_attn2<<<gfl, 256>>>(q, k, v, attn, 0);
    sgemm_ep<<<g512, 256>>>(attn, ca_wo, ca_bo, xb, xb, ROWS, EMBED, EMBED, EP_RES);
    layernorm_k<<<ROWS, 128>>>(xb, ln2_g, ln2_b, xb);

    // ---- feed-forward ----
    sgemm_ep<<<gff, 256>>>(xb, ff_w1, ff_b1, nullptr, hb, ROWS, FF, EMBED, EP_GELU);
    sgemm_ep<<<g512, 256>>>(hb, ff_w2, ff_b2, xb, xb, ROWS, EMBED, FF, EP_RES);
    layernorm_k<<<ROWS, 128>>>(xb, ln3_g, ln3_b, out);
}

// round 5
// speedup vs baseline: 2.4293x; 2.4293x over previous
#include <cuda_runtime.h>
#include <math.h>
#include <stdint.h>

#define EMBED 512
#define NH    8
#define DH    64
#define BATCH 2
#define SEQ   2048
#define ROWS  (BATCH*SEQ)   // 4096
#define FF    2048

// ---------------- scratch (no allocation allowed) ----------------
__device__ float g_q[ROWS*EMBED];
__device__ float g_k[ROWS*EMBED];
__device__ float g_v[ROWS*EMBED];
__device__ float g_attn[ROWS*EMBED];
__device__ float g_x[ROWS*EMBED];
__device__ float g_h[ROWS*FF];

#define EP_BIAS 0
#define EP_RES  1
#define EP_GELU 2

// ================= tf32 tensor-core GEMM =================
// C[M,N] = A[M,K] @ B[K,N] (+bias, +epilogue). Block tile 64x64x16,
// 128 threads = 4 warps in 2x2, each warp 32x32 via m16n8k8 tf32 mma.

#define GBM 64
#define GBN 64
#define GBK 16

__device__ __forceinline__ float to_tf32(float x) {
    float y;
    asm("cvt.rna.tf32.f32 %0, %1;" : "=f"(y) : "f"(x));
    return y;
}

__device__ __forceinline__ void mma_tf32(
    float c[4], const uint32_t a[4], const uint32_t b[2])
{
    asm volatile(
        "mma.sync.aligned.m16n8k8.row.col.f32.tf32.tf32.f32 "
        "{%0,%1,%2,%3}, {%4,%5,%6,%7}, {%8,%9}, {%0,%1,%2,%3};"
        : "+f"(c[0]), "+f"(c[1]), "+f"(c[2]), "+f"(c[3])
        : "r"(a[0]), "r"(a[1]), "r"(a[2]), "r"(a[3]), "r"(b[0]), "r"(b[1]));
}

__device__ __forceinline__ void tgemm_body(
    const float* __restrict__ A, const float* __restrict__ B,
    const float* __restrict__ bias, const float* __restrict__ R,
    float* __restrict__ C, int M, int N, int K, int ep,
    int bm, int bn)
{
    __shared__ float As[GBM][20];   // row-major A tile, stride 20 (conflict-free frags)
    __shared__ float Bs[GBK][72];   // row-major B tile, stride 72 (conflict-free frags)

    const int tid  = threadIdx.x;
    const int wid  = tid >> 5;
    const int lane = tid & 31;
    const int g    = lane >> 2;     // groupID 0..7
    const int tg   = lane & 3;      // thread-in-group 0..3
    const int warpM = (wid >> 1) * 32;
    const int warpN = (wid & 1) * 32;

    float c[2][4][4];
    #pragma unroll
    for (int mi = 0; mi < 2; mi++)
        #pragma unroll
        for (int ni = 0; ni < 4; ni++)
            #pragma unroll
            for (int r = 0; r < 4; r++) c[mi][ni][r] = 0.f;

    const int nkb = K / GBK;
    for (int kb = 0; kb < nkb; kb++) {
        const int k0 = kb * GBK;
        // ---- A tile: 64 rows x 16 cols = 256 float4, 2 per thread ----
        #pragma unroll
        for (int i = 0; i < 2; i++) {
            const int idx = tid + i * 128;
            const int row = idx >> 2;
            const int c4  = (idx & 3) * 4;
            float4 a = *(const float4*)(A + (size_t)(bm + row) * K + k0 + c4);
            a.x = to_tf32(a.x); a.y = to_tf32(a.y);
            a.z = to_tf32(a.z); a.w = to_tf32(a.w);
            *(float4*)(&As[row][c4]) = a;
        }
        // ---- B tile: 16 rows x 64 cols = 256 float4, 2 per thread ----
        #pragma unroll
        for (int i = 0; i < 2; i++) {
            const int idx = tid + i * 128;
            const int r  = idx >> 4;
            const int c4 = (idx & 15) * 4;
            float4 b = *(const float4*)(B + (size_t)(k0 + r) * N + bn + c4);
            b.x = to_tf32(b.x); b.y = to_tf32(b.y);
            b.z = to_tf32(b.z); b.w = to_tf32(b.w);
            *(float4*)(&Bs[r][c4]) = b;
        }
        __syncthreads();

        #pragma unroll
        for (int ks = 0; ks < GBK; ks += 8) {
            uint32_t af[2][4], bf[4][2];
            #pragma unroll
            for (int mi = 0; mi < 2; mi++) {
                const int m0 = warpM + mi * 16;
                af[mi][0] = __float_as_uint(As[m0 + g    ][ks + tg    ]);
                af[mi][1] = __float_as_uint(As[m0 + g + 8][ks + tg    ]);
                af[mi][2] = __float_as_uint(As[m0 + g    ][ks + tg + 4]);
                af[mi][3] = __float_as_uint(As[m0 + g + 8][ks + tg + 4]);
            }
            #pragma unroll
            for (int ni = 0; ni < 4; ni++) {
                const int n0 = warpN + ni * 8 + g;
                bf[ni][0] = __float_as_uint(Bs[ks + tg    ][n0]);
                bf[ni][1] = __float_as_uint(Bs[ks + tg + 4][n0]);
            }
            #pragma unroll
            for (int mi = 0; mi < 2; mi++)
                #pragma unroll
                for (int ni = 0; ni < 4; ni++)
                    mma_tf32(c[mi][ni], af[mi], bf[ni]);
        }
        __syncthreads();
    }

    // ---- epilogue ----
    #pragma unroll
    for (int mi = 0; mi < 2; mi++) {
        #pragma unroll
        for (int ni = 0; ni < 4; ni++) {
            const int col = bn + warpN + ni * 8 + tg * 2;
            const float b0 = bias[col], b1 = bias[col + 1];
            #pragma unroll
            for (int h = 0; h < 2; h++) {
                const int row = bm + warpM + mi * 16 + g + h * 8;
                float v0 = c[mi][ni][2 * h + 0] + b0;
                float v1 = c[mi][ni][2 * h + 1] + b1;
                if (ep == EP_RES) {
                    const float2 rr = *(const float2*)(R + (size_t)row * N + col);
                    v0 += rr.x; v1 += rr.y;
                } else if (ep == EP_GELU) {
                    v0 = 0.5f * v0 * (1.0f + erff(v0 * 0.70710678118654752f));
                    v1 = 0.5f * v1 * (1.0f + erff(v1 * 0.70710678118654752f));
                }
                *(float2*)(C + (size_t)row * N + col) = make_float2(v0, v1);
            }
        }
    }
}

__global__ __launch_bounds__(128) void tgemm_ep(
    const float* __restrict__ A, const float* __restrict__ B,
    const float* __restrict__ bias, const float* __restrict__ R,
    float* __restrict__ C, int M, int N, int K, int ep)
{
    tgemm_body(A, B, bias, R, C, M, N, K, ep,
               blockIdx.y * GBM, blockIdx.x * GBN);
}

// one launch for Q/K/V projections: blockIdx.z selects the GEMM
__global__ __launch_bounds__(128) void tgemm_qkv(
    const float* __restrict__ Aq, const float* __restrict__ Akv,
    const float* __restrict__ Wq, const float* __restrict__ bq,
    const float* __restrict__ Wk, const float* __restrict__ bk,
    const float* __restrict__ Wv, const float* __restrict__ bv,
    float* __restrict__ Cq, float* __restrict__ Ck, float* __restrict__ Cv)
{
    const int z = blockIdx.z;
    const float* A = (z == 0) ? Aq : Akv;
    const float* W = (z == 0) ? Wq : (z == 1) ? Wk : Wv;
    const float* bia = (z == 0) ? bq : (z == 1) ? bk : bv;
    float* C = (z == 0) ? Cq : (z == 1) ? Ck : Cv;
    tgemm_body(A, W, bia, nullptr, C, ROWS, EMBED, EMBED, EP_BIAS,
               blockIdx.y * GBM, blockIdx.x * GBN);
}

// ---------------- flash attention (fp32, one query per thread) --------------
// (reverted exactly to the R3 version: known 706us/launch)
#define TQ 128
#define TK 32

__global__ __launch_bounds__(128) void flash_attn(
    const float* __restrict__ Q, const float* __restrict__ Km,
    const float* __restrict__ V, float* __restrict__ O, int causal)
{
    __shared__ float sk[TK][DH];
    __shared__ float sv[TK][DH];
    const int b = blockIdx.z, h = blockIdx.y, qt = blockIdx.x;
    const int t = threadIdx.x;
    const int q = qt * TQ + t;
    const size_t qoff = ((size_t)(b * SEQ + q)) * EMBED + h * DH;

    float4 qv[DH / 4];
    #pragma unroll
    for (int i = 0; i < DH / 4; i++) {
        float4 x = *(const float4*)(Q + qoff + 4 * i);
        x.x *= 0.125f; x.y *= 0.125f; x.z *= 0.125f; x.w *= 0.125f;  // 1/sqrt(64)
        qv[i] = x;
    }
    float4 acc[DH / 4];
    #pragma unroll
    for (int i = 0; i < DH / 4; i++) acc[i] = make_float4(0.f, 0.f, 0.f, 0.f);
    float mi = -1e30f, li = 0.f;

    const int nkt = causal ? (qt + 1) * (TQ / TK) : SEQ / TK;
    for (int kt = 0; kt < nkt; kt++) {
        #pragma unroll
        for (int i = 0; i < 4; i++) {
            int idx = t + i * 128;
            int r = idx >> 4;
            int c = (idx & 15) * 4;
            size_t goff = ((size_t)(b * SEQ + kt * TK + r)) * EMBED + h * DH + c;
            *(float4*)(&sk[r][c]) = *(const float4*)(Km + goff);
            *(float4*)(&sv[r][c]) = *(const float4*)(V  + goff);
        }
        __syncthreads();

        float s[TK];
        float tmax = -1e30f;
        #pragma unroll
        for (int j = 0; j < TK; j++) {
            const int k = kt * TK + j;
            float d = -1e30f;
            if (!causal || k <= q) {
                float dd = 0.f;
                #pragma unroll
                for (int i = 0; i < DH / 4; i++) {
                    float4 kv = *(const float4*)(&sk[j][4 * i]);
                    dd += qv[i].x * kv.x + qv[i].y * kv.y + qv[i].z * kv.z + qv[i].w * kv.w;
                }
                d = dd;
            }
            s[j] = d;
            tmax = fmaxf(tmax, d);
        }
        const float mnew = fmaxf(mi, tmax);
        const float corr = __expf(mi - mnew);
        li *= corr;
        #pragma unroll
        for (int i = 0; i < DH / 4; i++) {
            acc[i].x *= corr; acc[i].y *= corr; acc[i].z *= corr; acc[i].w *= corr;
        }
        #pragma unroll
        for (int j = 0; j < TK; j++) {
            const float p = __expf(s[j] - mnew);
            li += p;
            #pragma unroll
            for (int i = 0; i < DH / 4; i++) {
                float4 vv = *(const float4*)(&sv[j][4 * i]);
                acc[i].x += p * vv.x; acc[i].y += p * vv.y;
                acc[i].z += p * vv.z; acc[i].w += p * vv.w;
            }
        }
        mi = mnew;
        __syncthreads();
    }
    const float inv = 1.f / li;
    #pragma unroll
    for (int i = 0; i < DH / 4; i++) {
        float4 o = acc[i];
        o.x *= inv; o.y *= inv; o.z *= inv; o.w *= inv;
        *(float4*)(O + qoff + 4 * i) = o;
    }
}

// ---------------- LayerNorm over last dim (512) -----------------------------
__global__ __launch_bounds__(128) void layernorm_k(
    const float* __restrict__ X, const float* __restrict__ G,
    const float* __restrict__ Bt, float* __restrict__ Y)
{
    const int row = blockIdx.x;
    const int t = threadIdx.x;
    const float* xr = X + (size_t)row * EMBED;
    float4 v = *(const float4*)(xr + t * 4);
    float s  = v.x + v.y + v.z + v.w;
    float ss = v.x * v.x + v.y * v.y + v.z * v.z + v.w * v.w;
    #pragma unroll
    for (int o = 16; o > 0; o >>= 1) {
        s  += __shfl_xor_sync(0xffffffffu, s,  o);
        ss += __shfl_xor_sync(0xffffffffu, ss, o);
    }
    __shared__ float sh_s[4], sh_ss[4];
    const int w = t >> 5;
    if ((t & 31) == 0) { sh_s[w] = s; sh_ss[w] = ss; }
    __syncthreads();
    s  = sh_s[0] + sh_s[1] + sh_s[2] + sh_s[3];
    ss = sh_ss[0] + sh_ss[1] + sh_ss[2] + sh_ss[3];
    const float mean = s * (1.f / EMBED);
    const float var  = ss * (1.f / EMBED) - mean * mean;
    const float rstd = rsqrtf(var + 1e-5f);
    float4 gg = *(const float4*)(G  + t * 4);
    float4 bb = *(const float4*)(Bt + t * 4);
    float4 o;
    o.x = (v.x - mean) * rstd * gg.x + bb.x;
    o.y = (v.y - mean) * rstd * gg.y + bb.y;
    o.z = (v.z - mean) * rstd * gg.z + bb.z;
    o.w = (v.w - mean) * rstd * gg.w + bb.w;
    *(float4*)(Y + (size_t)row * EMBED + t * 4) = o;
}

// ---------------- launch --------------------------------------------------
extern "C" void kernel_launch(void* const* d_in, const int* in_sizes, int n_in,
                              void* d_out, int out_size)
{
    const float* x     = (const float*)d_in[0];
    const float* enc   = (const float*)d_in[1];
    const float* sa_wq = (const float*)d_in[2];
    const float* sa_bq = (const float*)d_in[3];
    const float* sa_wk = (const float*)d_in[4];
    const float* sa_bk = (const float*)d_in[5];
    const float* sa_wv = (const float*)d_in[6];
    const float* sa_bv = (const float*)d_in[7];
    const float* sa_wo = (const float*)d_in[8];
    const float* sa_bo = (const float*)d_in[9];
    const float* ca_wq = (const float*)d_in[10];
    const float* ca_bq = (const float*)d_in[11];
    const float* ca_wk = (const float*)d_in[12];
    const float* ca_bk = (const float*)d_in[13];
    const float* ca_wv = (const float*)d_in[14];
    const float* ca_bv = (const float*)d_in[15];
    const float* ca_wo = (const float*)d_in[16];
    const float* ca_bo = (const float*)d_in[17];
    const float* ln1_g = (const float*)d_in[18];
    const float* ln1_b = (const float*)d_in[19];
    const float* ln2_g = (const float*)d_in[20];
    const float* ln2_b = (const float*)d_in[21];
    const float* ln3_g = (const float*)d_in[22];
    const float* ln3_b = (const float*)d_in[23];
    const float* ff_w1 = (const float*)d_in[24];
    const float* ff_b1 = (const float*)d_in[25];
    const float* ff_w2 = (const float*)d_in[26];
    const float* ff_b2 = (const float*)d_in[27];
    float* out = (float*)d_out;

    float *q, *k, *v, *attn, *xb, *hb;
    cudaGetSymbolAddress((void**)&q,    g_q);
    cudaGetSymbolAddress((void**)&k,    g_k);
    cudaGetSymbolAddress((void**)&v,    g_v);
    cudaGetSymbolAddress((void**)&attn, g_attn);
    cudaGetSymbolAddress((void**)&xb,   g_x);
    cudaGetSymbolAddress((void**)&hb,   g_h);

    dim3 g512(EMBED / GBN, ROWS / GBM);      // (8, 64)
    dim3 gqkv(EMBED / GBN, ROWS / GBM, 3);   // (8, 64, 3)
    dim3 gff (FF    / GBN, ROWS / GBM);      // (32, 64)
    dim3 gfl (SEQ / TQ, NH, BATCH);          // (16, 8, 2)

    // ---- self attention (causal) ----
    tgemm_qkv<<<gqkv, 128>>>(x, x, sa_wq, sa_bq, sa_wk, sa_bk, sa_wv, sa_bv, q, k, v);
    flash_attn<<<gfl, 128>>>(q, k, v, attn, 1);
    tgemm_ep<<<g512, 128>>>(attn, sa_wo, sa_bo, x, xb, ROWS, EMBED, EMBED, EP_RES);
    layernorm_k<<<ROWS, 128>>>(xb, ln1_g, ln1_b, xb);

    // ---- cross attention ----
    tgemm_qkv<<<gqkv, 128>>>(xb, enc, ca_wq, ca_bq, ca_wk, ca_bk, ca_wv, ca_bv, q, k, v);
    flash_attn<<<gfl, 128>>>(q, k, v, attn, 0);
    tgemm_ep<<<g512, 128>>>(attn, ca_wo, ca_bo, xb, xb, ROWS, EMBED, EMBED, EP_RES);
    layernorm_k<<<ROWS, 128>>>(xb, ln2_g, ln2_b, xb);

    // ---- feed-forward ----
    tgemm_ep<<<gff, 128>>>(xb, ff_w1, ff_b1, nullptr, hb, ROWS, FF, EMBED, EP_GELU);
    tgemm_ep<<<g512, 128>>>(hb, ff_w2, ff_b2, xb, xb, ROWS, EMBED, FF, EP_RES);
    layernorm_k<<<ROWS, 128>>>(xb, ln3_g, ln3_b, out);
}

// round 6
// speedup vs baseline: 5.9862x; 2.4641x over previous
#include <cuda_runtime.h>
#include <math.h>
#include <stdint.h>

#define EMBED 512
#define NH    8
#define DH    64
#define BATCH 2
#define SEQ   2048
#define ROWS  (BATCH*SEQ)   // 4096
#define FF    2048

// ---------------- scratch (no allocation allowed) ----------------
__device__ float g_q[ROWS*EMBED];
__device__ float g_k[ROWS*EMBED];
__device__ float g_v[ROWS*EMBED];
__device__ float g_attn[ROWS*EMBED];
__device__ float g_x[ROWS*EMBED];
__device__ float g_h[ROWS*FF];

#define EP_BIAS 0
#define EP_RES  1
#define EP_GELU 2

__device__ __forceinline__ float to_tf32(float x) {
    float y;
    asm("cvt.rna.tf32.f32 %0, %1;" : "=f"(y) : "f"(x));
    return y;
}

__device__ __forceinline__ void mma_tf32(
    float c[4], const uint32_t a[4], const uint32_t b[2])
{
    asm volatile(
        "mma.sync.aligned.m16n8k8.row.col.f32.tf32.tf32.f32 "
        "{%0,%1,%2,%3}, {%4,%5,%6,%7}, {%8,%9}, {%0,%1,%2,%3};"
        : "+f"(c[0]), "+f"(c[1]), "+f"(c[2]), "+f"(c[3])
        : "r"(a[0]), "r"(a[1]), "r"(a[2]), "r"(a[3]), "r"(b[0]), "r"(b[1]));
}

// ================= tf32 tensor-core GEMM (unchanged from R5) =================
#define GBM 64
#define GBN 64
#define GBK 16

__device__ __forceinline__ void tgemm_body(
    const float* __restrict__ A, const float* __restrict__ B,
    const float* __restrict__ bias, const float* __restrict__ R,
    float* __restrict__ C, int M, int N, int K, int ep,
    int bm, int bn)
{
    __shared__ float As[GBM][20];
    __shared__ float Bs[GBK][72];

    const int tid  = threadIdx.x;
    const int wid  = tid >> 5;
    const int lane = tid & 31;
    const int g    = lane >> 2;
    const int tg   = lane & 3;
    const int warpM = (wid >> 1) * 32;
    const int warpN = (wid & 1) * 32;

    float c[2][4][4];
    #pragma unroll
    for (int mi = 0; mi < 2; mi++)
        #pragma unroll
        for (int ni = 0; ni < 4; ni++)
            #pragma unroll
            for (int r = 0; r < 4; r++) c[mi][ni][r] = 0.f;

    const int nkb = K / GBK;
    for (int kb = 0; kb < nkb; kb++) {
        const int k0 = kb * GBK;
        #pragma unroll
        for (int i = 0; i < 2; i++) {
            const int idx = tid + i * 128;
            const int row = idx >> 2;
            const int c4  = (idx & 3) * 4;
            float4 a = *(const float4*)(A + (size_t)(bm + row) * K + k0 + c4);
            a.x = to_tf32(a.x); a.y = to_tf32(a.y);
            a.z = to_tf32(a.z); a.w = to_tf32(a.w);
            *(float4*)(&As[row][c4]) = a;
        }
        #pragma unroll
        for (int i = 0; i < 2; i++) {
            const int idx = tid + i * 128;
            const int r  = idx >> 4;
            const int c4 = (idx & 15) * 4;
            float4 b = *(const float4*)(B + (size_t)(k0 + r) * N + bn + c4);
            b.x = to_tf32(b.x); b.y = to_tf32(b.y);
            b.z = to_tf32(b.z); b.w = to_tf32(b.w);
            *(float4*)(&Bs[r][c4]) = b;
        }
        __syncthreads();

        #pragma unroll
        for (int ks = 0; ks < GBK; ks += 8) {
            uint32_t af[2][4], bf[4][2];
            #pragma unroll
            for (int mi = 0; mi < 2; mi++) {
                const int m0 = warpM + mi * 16;
                af[mi][0] = __float_as_uint(As[m0 + g    ][ks + tg    ]);
                af[mi][1] = __float_as_uint(As[m0 + g + 8][ks + tg    ]);
                af[mi][2] = __float_as_uint(As[m0 + g    ][ks + tg + 4]);
                af[mi][3] = __float_as_uint(As[m0 + g + 8][ks + tg + 4]);
            }
            #pragma unroll
            for (int ni = 0; ni < 4; ni++) {
                const int n0 = warpN + ni * 8 + g;
                bf[ni][0] = __float_as_uint(Bs[ks + tg    ][n0]);
                bf[ni][1] = __float_as_uint(Bs[ks + tg + 4][n0]);
            }
            #pragma unroll
            for (int mi = 0; mi < 2; mi++)
                #pragma unroll
                for (int ni = 0; ni < 4; ni++)
                    mma_tf32(c[mi][ni], af[mi], bf[ni]);
        }
        __syncthreads();
    }

    #pragma unroll
    for (int mi = 0; mi < 2; mi++) {
        #pragma unroll
        for (int ni = 0; ni < 4; ni++) {
            const int col = bn + warpN + ni * 8 + tg * 2;
            const float b0 = bias[col], b1 = bias[col + 1];
            #pragma unroll
            for (int h = 0; h < 2; h++) {
                const int row = bm + warpM + mi * 16 + g + h * 8;
                float v0 = c[mi][ni][2 * h + 0] + b0;
                float v1 = c[mi][ni][2 * h + 1] + b1;
                if (ep == EP_RES) {
                    const float2 rr = *(const float2*)(R + (size_t)row * N + col);
                    v0 += rr.x; v1 += rr.y;
                } else if (ep == EP_GELU) {
                    v0 = 0.5f * v0 * (1.0f + erff(v0 * 0.70710678118654752f));
                    v1 = 0.5f * v1 * (1.0f + erff(v1 * 0.70710678118654752f));
                }
                *(float2*)(C + (size_t)row * N + col) = make_float2(v0, v1);
            }
        }
    }
}

__global__ __launch_bounds__(128) void tgemm_ep(
    const float* __restrict__ A, const float* __restrict__ B,
    const float* __restrict__ bias, const float* __restrict__ R,
    float* __restrict__ C, int M, int N, int K, int ep)
{
    tgemm_body(A, B, bias, R, C, M, N, K, ep,
               blockIdx.y * GBM, blockIdx.x * GBN);
}

__global__ __launch_bounds__(128) void tgemm_qkv(
    const float* __restrict__ Aq, const float* __restrict__ Akv,
    const float* __restrict__ Wq, const float* __restrict__ bq,
    const float* __restrict__ Wk, const float* __restrict__ bk,
    const float* __restrict__ Wv, const float* __restrict__ bv,
    float* __restrict__ Cq, float* __restrict__ Ck, float* __restrict__ Cv)
{
    const int z = blockIdx.z;
    const float* A = (z == 0) ? Aq : Akv;
    const float* W = (z == 0) ? Wq : (z == 1) ? Wk : Wv;
    const float* bia = (z == 0) ? bq : (z == 1) ? bk : bv;
    float* C = (z == 0) ? Cq : (z == 1) ? Ck : Cv;
    tgemm_body(A, W, bia, nullptr, C, ROWS, EMBED, EMBED, EP_BIAS,
               blockIdx.y * GBM, blockIdx.x * GBN);
}

// ================= tf32 tensor-core flash attention =================
// CTA: 64 queries x 1 head. 4 warps, warp w owns query rows w*16..w*16+15.
// S = Q K^T and O += P V via mma.m16n8k8.tf32. Online softmax on fragments.
#define ATQ 64
#define ATK 64
#define QS_STRIDE 68   // g-major fragment reads: (g*68+tg) mod 32 = 4g+tg distinct
#define VS_STRIDE 72   // tg-major fragment reads: (tg*72+g) mod 32 = 8tg+g distinct
#define FA_SMEM ((2*ATQ*QS_STRIDE + ATK*VS_STRIDE) * 4)   // 53248 bytes

__global__ __launch_bounds__(128) void flash_mma(
    const float* __restrict__ Q, const float* __restrict__ Km,
    const float* __restrict__ V, float* __restrict__ O, int causal)
{
    extern __shared__ float sm[];
    float* Qs = sm;                          // [64][68], reused as P after prologue
    float* Ks = sm + ATQ * QS_STRIDE;        // [64][68]
    float* Vs = Ks + ATK * QS_STRIDE;        // [64][72]

    const int b = blockIdx.z, h = blockIdx.y, qb = blockIdx.x;
    const int tid = threadIdx.x;
    const int wid = tid >> 5, lane = tid & 31;
    const int g = lane >> 2, tg = lane & 3;
    const int qbase = qb * ATQ;
    const int m0 = wid * 16;

    // ---- Q tile -> smem (scaled by 1/sqrt(64), tf32) ----
    #pragma unroll
    for (int i = 0; i < 8; i++) {
        const int idx = tid + i * 128;
        const int r = idx >> 4;
        const int c = (idx & 15) * 4;
        float4 qv = *(const float4*)(Q + ((size_t)(b * SEQ + qbase + r)) * EMBED + h * DH + c);
        qv.x = to_tf32(qv.x * 0.125f); qv.y = to_tf32(qv.y * 0.125f);
        qv.z = to_tf32(qv.z * 0.125f); qv.w = to_tf32(qv.w * 0.125f);
        *(float4*)(&Qs[r * QS_STRIDE + c]) = qv;
    }
    __syncthreads();

    // ---- Q fragments to registers (warp reads only its own 16 rows) ----
    uint32_t qf[8][4];
    #pragma unroll
    for (int ks = 0; ks < 8; ks++) {
        qf[ks][0] = __float_as_uint(Qs[(m0 + g    ) * QS_STRIDE + ks * 8 + tg    ]);
        qf[ks][1] = __float_as_uint(Qs[(m0 + g + 8) * QS_STRIDE + ks * 8 + tg    ]);
        qf[ks][2] = __float_as_uint(Qs[(m0 + g    ) * QS_STRIDE + ks * 8 + tg + 4]);
        qf[ks][3] = __float_as_uint(Qs[(m0 + g + 8) * QS_STRIDE + ks * 8 + tg + 4]);
    }
    // Qs rows m0..m0+15 now dead for this warp; reused as its private P region.

    float oacc[8][4];
    #pragma unroll
    for (int ni = 0; ni < 8; ni++)
        #pragma unroll
        for (int r = 0; r < 4; r++) oacc[ni][r] = 0.f;
    float m0r = -1e30f, m1r = -1e30f, l0r = 0.f, l1r = 0.f;

    const int nkt = causal ? (qb + 1) : (SEQ / ATK);
    for (int kt = 0; kt < nkt; kt++) {
        // ---- K/V tiles -> smem (tf32) ----
        #pragma unroll
        for (int i = 0; i < 8; i++) {
            const int idx = tid + i * 128;
            const int r = idx >> 4;
            const int c = (idx & 15) * 4;
            const size_t go = ((size_t)(b * SEQ + kt * ATK + r)) * EMBED + h * DH + c;
            float4 kk = *(const float4*)(Km + go);
            kk.x = to_tf32(kk.x); kk.y = to_tf32(kk.y);
            kk.z = to_tf32(kk.z); kk.w = to_tf32(kk.w);
            *(float4*)(&Ks[r * QS_STRIDE + c]) = kk;
            float4 vv = *(const float4*)(V + go);
            vv.x = to_tf32(vv.x); vv.y = to_tf32(vv.y);
            vv.z = to_tf32(vv.z); vv.w = to_tf32(vv.w);
            *(float4*)(&Vs[r * VS_STRIDE + c]) = vv;
        }
        __syncthreads();

        // ---- S = Q K^T ----
        float sacc[8][4];
        #pragma unroll
        for (int ni = 0; ni < 8; ni++)
            #pragma unroll
            for (int r = 0; r < 4; r++) sacc[ni][r] = 0.f;
        #pragma unroll
        for (int ks = 0; ks < 8; ks++) {
            #pragma unroll
            for (int ni = 0; ni < 8; ni++) {
                uint32_t bf[2];
                bf[0] = __float_as_uint(Ks[(ni * 8 + g) * QS_STRIDE + ks * 8 + tg    ]);
                bf[1] = __float_as_uint(Ks[(ni * 8 + g) * QS_STRIDE + ks * 8 + tg + 4]);
                mma_tf32(sacc[ni], qf[ks], bf);
            }
        }

        // ---- causal mask (only the diagonal tile needs it) ----
        if (causal && kt == qb) {
            const int r0 = qbase + m0 + g, r1 = r0 + 8;
            #pragma unroll
            for (int ni = 0; ni < 8; ni++) {
                const int c0 = kt * ATK + ni * 8 + 2 * tg;
                if (c0     > r0) sacc[ni][0] = -1e30f;
                if (c0 + 1 > r0) sacc[ni][1] = -1e30f;
                if (c0     > r1) sacc[ni][2] = -1e30f;
                if (c0 + 1 > r1) sacc[ni][3] = -1e30f;
            }
        }

        // ---- online softmax ----
        float mx0 = -1e30f, mx1 = -1e30f;
        #pragma unroll
        for (int ni = 0; ni < 8; ni++) {
            mx0 = fmaxf(mx0, fmaxf(sacc[ni][0], sacc[ni][1]));
            mx1 = fmaxf(mx1, fmaxf(sacc[ni][2], sacc[ni][3]));
        }
        mx0 = fmaxf(mx0, __shfl_xor_sync(0xffffffffu, mx0, 1));
        mx0 = fmaxf(mx0, __shfl_xor_sync(0xffffffffu, mx0, 2));
        mx1 = fmaxf(mx1, __shfl_xor_sync(0xffffffffu, mx1, 1));
        mx1 = fmaxf(mx1, __shfl_xor_sync(0xffffffffu, mx1, 2));
        const float mn0 = fmaxf(m0r, mx0);
        const float mn1 = fmaxf(m1r, mx1);
        const float cr0 = __expf(m0r - mn0);
        const float cr1 = __expf(m1r - mn1);
        m0r = mn0; m1r = mn1;

        float ls0 = 0.f, ls1 = 0.f;
        #pragma unroll
        for (int ni = 0; ni < 8; ni++) {
            const float p0 = __expf(sacc[ni][0] - mn0);
            const float p1 = __expf(sacc[ni][1] - mn0);
            const float p2 = __expf(sacc[ni][2] - mn1);
            const float p3 = __expf(sacc[ni][3] - mn1);
            ls0 += p0 + p1; ls1 += p2 + p3;
            *(float2*)(&Qs[(m0 + g    ) * QS_STRIDE + ni * 8 + 2 * tg]) =
                make_float2(to_tf32(p0), to_tf32(p1));
            *(float2*)(&Qs[(m0 + g + 8) * QS_STRIDE + ni * 8 + 2 * tg]) =
                make_float2(to_tf32(p2), to_tf32(p3));
        }
        ls0 += __shfl_xor_sync(0xffffffffu, ls0, 1);
        ls0 += __shfl_xor_sync(0xffffffffu, ls0, 2);
        ls1 += __shfl_xor_sync(0xffffffffu, ls1, 1);
        ls1 += __shfl_xor_sync(0xffffffffu, ls1, 2);
        l0r = l0r * cr0 + ls0;
        l1r = l1r * cr1 + ls1;

        #pragma unroll
        for (int ni = 0; ni < 8; ni++) {
            oacc[ni][0] *= cr0; oacc[ni][1] *= cr0;
            oacc[ni][2] *= cr1; oacc[ni][3] *= cr1;
        }
        __syncwarp();   // P region is per-warp private: warp-level ordering suffices

        // ---- O += P V ----
        #pragma unroll
        for (int ks = 0; ks < 8; ks++) {
            uint32_t af[4];
            af[0] = __float_as_uint(Qs[(m0 + g    ) * QS_STRIDE + ks * 8 + tg    ]);
            af[1] = __float_as_uint(Qs[(m0 + g + 8) * QS_STRIDE + ks * 8 + tg    ]);
            af[2] = __float_as_uint(Qs[(m0 + g    ) * QS_STRIDE + ks * 8 + tg + 4]);
            af[3] = __float_as_uint(Qs[(m0 + g + 8) * QS_STRIDE + ks * 8 + tg + 4]);
            #pragma unroll
            for (int ni = 0; ni < 8; ni++) {
                uint32_t bf[2];
                bf[0] = __float_as_uint(Vs[(ks * 8 + tg    ) * VS_STRIDE + ni * 8 + g]);
                bf[1] = __float_as_uint(Vs[(ks * 8 + tg + 4) * VS_STRIDE + ni * 8 + g]);
                mma_tf32(oacc[ni], af, bf);
            }
        }
        __syncthreads();   // before overwriting K/V tiles
    }

    const float inv0 = 1.f / l0r, inv1 = 1.f / l1r;
    #pragma unroll
    for (int ni = 0; ni < 8; ni++) {
        const size_t o0 = ((size_t)(b * SEQ + qbase + m0 + g)) * EMBED + h * DH + ni * 8 + 2 * tg;
        *(float2*)(O + o0)             = make_float2(oacc[ni][0] * inv0, oacc[ni][1] * inv0);
        *(float2*)(O + o0 + 8 * EMBED) = make_float2(oacc[ni][2] * inv1, oacc[ni][3] * inv1);
    }
}

// ---------------- LayerNorm over last dim (512) -----------------------------
__global__ __launch_bounds__(128) void layernorm_k(
    const float* __restrict__ X, const float* __restrict__ G,
    const float* __restrict__ Bt, float* __restrict__ Y)
{
    const int row = blockIdx.x;
    const int t = threadIdx.x;
    const float* xr = X + (size_t)row * EMBED;
    float4 v = *(const float4*)(xr + t * 4);
    float s  = v.x + v.y + v.z + v.w;
    float ss = v.x * v.x + v.y * v.y + v.z * v.z + v.w * v.w;
    #pragma unroll
    for (int o = 16; o > 0; o >>= 1) {
        s  += __shfl_xor_sync(0xffffffffu, s,  o);
        ss += __shfl_xor_sync(0xffffffffu, ss, o);
    }
    __shared__ float sh_s[4], sh_ss[4];
    const int w = t >> 5;
    if ((t & 31) == 0) { sh_s[w] = s; sh_ss[w] = ss; }
    __syncthreads();
    s  = sh_s[0] + sh_s[1] + sh_s[2] + sh_s[3];
    ss = sh_ss[0] + sh_ss[1] + sh_ss[2] + sh_ss[3];
    const float mean = s * (1.f / EMBED);
    const float var  = ss * (1.f / EMBED) - mean * mean;
    const float rstd = rsqrtf(var + 1e-5f);
    float4 gg = *(const float4*)(G  + t * 4);
    float4 bb = *(const float4*)(Bt + t * 4);
    float4 o;
    o.x = (v.x - mean) * rstd * gg.x + bb.x;
    o.y = (v.y - mean) * rstd * gg.y + bb.y;
    o.z = (v.z - mean) * rstd * gg.z + bb.z;
    o.w = (v.w - mean) * rstd * gg.w + bb.w;
    *(float4*)(Y + (size_t)row * EMBED + t * 4) = o;
}

// ---------------- launch --------------------------------------------------
extern "C" void kernel_launch(void* const* d_in, const int* in_sizes, int n_in,
                              void* d_out, int out_size)
{
    const float* x     = (const float*)d_in[0];
    const float* enc   = (const float*)d_in[1];
    const float* sa_wq = (const float*)d_in[2];
    const float* sa_bq = (const float*)d_in[3];
    const float* sa_wk = (const float*)d_in[4];
    const float* sa_bk = (const float*)d_in[5];
    const float* sa_wv = (const float*)d_in[6];
    const float* sa_bv = (const float*)d_in[7];
    const float* sa_wo = (const float*)d_in[8];
    const float* sa_bo = (const float*)d_in[9];
    const float* ca_wq = (const float*)d_in[10];
    const float* ca_bq = (const float*)d_in[11];
    const float* ca_wk = (const float*)d_in[12];
    const float* ca_bk = (const float*)d_in[13];
    const float* ca_wv = (const float*)d_in[14];
    const float* ca_bv = (const float*)d_in[15];
    const float* ca_wo = (const float*)d_in[16];
    const float* ca_bo = (const float*)d_in[17];
    const float* ln1_g = (const float*)d_in[18];
    const float* ln1_b = (const float*)d_in[19];
    const float* ln2_g = (const float*)d_in[20];
    const float* ln2_b = (const float*)d_in[21];
    const float* ln3_g = (const float*)d_in[22];
    const float* ln3_b = (const float*)d_in[23];
    const float* ff_w1 = (const float*)d_in[24];
    const float* ff_b1 = (const float*)d_in[25];
    const float* ff_w2 = (const float*)d_in[26];
    const float* ff_b2 = (const float*)d_in[27];
    float* out = (float*)d_out;

    float *q, *k, *v, *attn, *xb, *hb;
    cudaGetSymbolAddress((void**)&q,    g_q);
    cudaGetSymbolAddress((void**)&k,    g_k);
    cudaGetSymbolAddress((void**)&v,    g_v);
    cudaGetSymbolAddress((void**)&attn, g_attn);
    cudaGetSymbolAddress((void**)&xb,   g_x);
    cudaGetSymbolAddress((void**)&hb,   g_h);

    static int fa_attr_set = 0;
    if (!fa_attr_set) {
        cudaFuncSetAttribute(flash_mma,
                             cudaFuncAttributeMaxDynamicSharedMemorySize, FA_SMEM);
        fa_attr_set = 1;
    }

    dim3 g512(EMBED / GBN, ROWS / GBM);      // (8, 64)
    dim3 gqkv(EMBED / GBN, ROWS / GBM, 3);   // (8, 64, 3)
    dim3 gff (FF    / GBN, ROWS / GBM);      // (32, 64)
    dim3 gfl (SEQ / ATQ, NH, BATCH);         // (32, 8, 2)

    // ---- self attention (causal) ----
    tgemm_qkv<<<gqkv, 128>>>(x, x, sa_wq, sa_bq, sa_wk, sa_bk, sa_wv, sa_bv, q, k, v);
    flash_mma<<<gfl, 128, FA_SMEM>>>(q, k, v, attn, 1);
    tgemm_ep<<<g512, 128>>>(attn, sa_wo, sa_bo, x, xb, ROWS, EMBED, EMBED, EP_RES);
    layernorm_k<<<ROWS, 128>>>(xb, ln1_g, ln1_b, xb);

    // ---- cross attention ----
    tgemm_qkv<<<gqkv, 128>>>(xb, enc, ca_wq, ca_bq, ca_wk, ca_bk, ca_wv, ca_bv, q, k, v);
    flash_mma<<<gfl, 128, FA_SMEM>>>(q, k, v, attn, 0);
    tgemm_ep<<<g512, 128>>>(attn, ca_wo, ca_bo, xb, xb, ROWS, EMBED, EMBED, EP_RES);
    layernorm_k<<<ROWS, 128>>>(xb, ln2_g, ln2_b, xb);

    // ---- feed-forward ----
    tgemm_ep<<<gff, 128>>>(xb, ff_w1, ff_b1, nullptr, hb, ROWS, FF, EMBED, EP_GELU);
    tgemm_ep<<<g512, 128>>>(hb, ff_w2, ff_b2, xb, xb, ROWS, EMBED, FF, EP_RES);
    layernorm_k<<<ROWS, 128>>>(xb, ln3_g, ln3_b, out);
}

// round 7
// speedup vs baseline: 6.4503x; 1.0775x over previous
#include <cuda_runtime.h>
#include <math.h>
#include <stdint.h>

#define EMBED 512
#define NH    8
#define DH    64
#define BATCH 2
#define SEQ   2048
#define ROWS  (BATCH*SEQ)   // 4096
#define FF    2048

// ---------------- scratch (no allocation allowed) ----------------
__device__ float g_q[ROWS*EMBED];
__device__ float g_k[ROWS*EMBED];
__device__ float g_v[ROWS*EMBED];
__device__ float g_attn[ROWS*EMBED];
__device__ float g_x[ROWS*EMBED];
__device__ float g_h[ROWS*FF];

#define EP_BIAS 0
#define EP_RES  1
#define EP_GELU 2

__device__ __forceinline__ float to_tf32(float x) {
    float y;
    asm("cvt.rna.tf32.f32 %0, %1;" : "=f"(y) : "f"(x));
    return y;
}

__device__ __forceinline__ void mma_tf32(
    float c[4], const uint32_t a[4], const uint32_t b[2])
{
    asm volatile(
        "mma.sync.aligned.m16n8k8.row.col.f32.tf32.tf32.f32 "
        "{%0,%1,%2,%3}, {%4,%5,%6,%7}, {%8,%9}, {%0,%1,%2,%3};"
        : "+f"(c[0]), "+f"(c[1]), "+f"(c[2]), "+f"(c[3])
        : "r"(a[0]), "r"(a[1]), "r"(a[2]), "r"(a[3]), "r"(b[0]), "r"(b[1]));
}

__device__ __forceinline__ void cpasync16(void* sptr, const void* gptr) {
    uint32_t s = (uint32_t)__cvta_generic_to_shared(sptr);
    asm volatile("cp.async.ca.shared.global [%0], [%1], 16;\n" :: "r"(s), "l"(gptr));
}
__device__ __forceinline__ void cpasync_commit() {
    asm volatile("cp.async.commit_group;\n" ::: "memory");
}
template <int N>
__device__ __forceinline__ void cpasync_wait() {
    asm volatile("cp.async.wait_group %0;\n" :: "n"(N) : "memory");
}

// ================= tf32 tensor-core GEMM, cp.async double-buffered ==========
// Block tile 128x64x16, 256 threads = 8 warps in 4x2, each warp 32x32.
// Raw fp32 bits fed to tf32 MMA (implicit truncation — cutlass fast path).
#define GBM 128
#define GBN 64
#define GBK 16
#define AS_STRIDE 20
#define BS_STRIDE 72

__device__ __forceinline__ void tgemm_body(
    const float* __restrict__ A, const float* __restrict__ B,
    const float* __restrict__ bias, const float* __restrict__ R,
    float* __restrict__ C, int M, int N, int K, int ep,
    int bm, int bn)
{
    __shared__ float As[2][GBM][AS_STRIDE];   // 2 x 10240 B
    __shared__ float Bs[2][GBK][BS_STRIDE];   // 2 x 4608 B

    const int tid  = threadIdx.x;
    const int wid  = tid >> 5;
    const int lane = tid & 31;
    const int g    = lane >> 2;
    const int tg   = lane & 3;
    const int warpM = (wid >> 1) * 32;   // 0,32,64,96
    const int warpN = (wid & 1) * 32;    // 0,32

    // per-thread load coords
    const int aRow = tid >> 1;           // 0..127
    const int aC4  = (tid & 1) * 8;      // 0 or 8 (two float4 slots per row-half)
    const int bRow = tid >> 4;           // 0..15
    const int bC4  = (tid & 15) * 4;     // 0..60

    float c[2][4][4];
    #pragma unroll
    for (int mi = 0; mi < 2; mi++)
        #pragma unroll
        for (int ni = 0; ni < 4; ni++)
            #pragma unroll
            for (int r = 0; r < 4; r++) c[mi][ni][r] = 0.f;

    const int nkb = K / GBK;

    // prologue: stage 0
    {
        cpasync16(&As[0][aRow][aC4],     A + (size_t)(bm + aRow) * K + aC4);
        cpasync16(&As[0][aRow][aC4 + 4], A + (size_t)(bm + aRow) * K + aC4 + 4);
        cpasync16(&Bs[0][bRow][bC4],     B + (size_t)bRow * N + bn + bC4);
        cpasync_commit();
    }

    for (int kb = 0; kb < nkb; kb++) {
        const int cur = kb & 1;
        if (kb + 1 < nkb) {
            const int nxt = cur ^ 1;
            const int k0 = (kb + 1) * GBK;
            cpasync16(&As[nxt][aRow][aC4],     A + (size_t)(bm + aRow) * K + k0 + aC4);
            cpasync16(&As[nxt][aRow][aC4 + 4], A + (size_t)(bm + aRow) * K + k0 + aC4 + 4);
            cpasync16(&Bs[nxt][bRow][bC4],     B + (size_t)(k0 + bRow) * N + bn + bC4);
            cpasync_commit();
            cpasync_wait<1>();
        } else {
            cpasync_wait<0>();
        }
        __syncthreads();

        #pragma unroll
        for (int ks = 0; ks < GBK; ks += 8) {
            uint32_t af[2][4], bf[4][2];
            #pragma unroll
            for (int mi = 0; mi < 2; mi++) {
                const int m0 = warpM + mi * 16;
                af[mi][0] = __float_as_uint(As[cur][m0 + g    ][ks + tg    ]);
                af[mi][1] = __float_as_uint(As[cur][m0 + g + 8][ks + tg    ]);
                af[mi][2] = __float_as_uint(As[cur][m0 + g    ][ks + tg + 4]);
                af[mi][3] = __float_as_uint(As[cur][m0 + g + 8][ks + tg + 4]);
            }
            #pragma unroll
            for (int ni = 0; ni < 4; ni++) {
                const int n0 = warpN + ni * 8 + g;
                bf[ni][0] = __float_as_uint(Bs[cur][ks + tg    ][n0]);
                bf[ni][1] = __float_as_uint(Bs[cur][ks + tg + 4][n0]);
            }
            #pragma unroll
            for (int mi = 0; mi < 2; mi++)
                #pragma unroll
                for (int ni = 0; ni < 4; ni++)
                    mma_tf32(c[mi][ni], af[mi], bf[ni]);
        }
        __syncthreads();   // buffer 'cur' may be refilled next iteration
    }

    // ---- epilogue ----
    #pragma unroll
    for (int mi = 0; mi < 2; mi++) {
        #pragma unroll
        for (int ni = 0; ni < 4; ni++) {
            const int col = bn + warpN + ni * 8 + tg * 2;
            const float b0 = bias[col], b1 = bias[col + 1];
            #pragma unroll
            for (int h = 0; h < 2; h++) {
                const int row = bm + warpM + mi * 16 + g + h * 8;
                float v0 = c[mi][ni][2 * h + 0] + b0;
                float v1 = c[mi][ni][2 * h + 1] + b1;
                if (ep == EP_RES) {
                    const float2 rr = *(const float2*)(R + (size_t)row * N + col);
                    v0 += rr.x; v1 += rr.y;
                } else if (ep == EP_GELU) {
                    v0 = 0.5f * v0 * (1.0f + erff(v0 * 0.70710678118654752f));
                    v1 = 0.5f * v1 * (1.0f + erff(v1 * 0.70710678118654752f));
                }
                *(float2*)(C + (size_t)row * N + col) = make_float2(v0, v1);
            }
        }
    }
}

__global__ __launch_bounds__(256) void tgemm_ep(
    const float* __restrict__ A, const float* __restrict__ B,
    const float* __restrict__ bias, const float* __restrict__ R,
    float* __restrict__ C, int M, int N, int K, int ep)
{
    tgemm_body(A, B, bias, R, C, M, N, K, ep,
               blockIdx.y * GBM, blockIdx.x * GBN);
}

__global__ __launch_bounds__(256) void tgemm_qkv(
    const float* __restrict__ Aq, const float* __restrict__ Akv,
    const float* __restrict__ Wq, const float* __restrict__ bq,
    const float* __restrict__ Wk, const float* __restrict__ bk,
    const float* __restrict__ Wv, const float* __restrict__ bv,
    float* __restrict__ Cq, float* __restrict__ Ck, float* __restrict__ Cv)
{
    const int z = blockIdx.z;
    const float* A = (z == 0) ? Aq : Akv;
    const float* W = (z == 0) ? Wq : (z == 1) ? Wk : Wv;
    const float* bia = (z == 0) ? bq : (z == 1) ? bk : bv;
    float* C = (z == 0) ? Cq : (z == 1) ? Ck : Cv;
    tgemm_body(A, W, bia, nullptr, C, ROWS, EMBED, EMBED, EP_BIAS,
               blockIdx.y * GBM, blockIdx.x * GBN);
}

// ================= tf32 tensor-core flash attention (unchanged R6) ==========
#define ATQ 64
#define ATK 64
#define QS_STRIDE 68
#define VS_STRIDE 72
#define FA_SMEM ((2*ATQ*QS_STRIDE + ATK*VS_STRIDE) * 4)   // 53248 bytes

__global__ __launch_bounds__(128) void flash_mma(
    const float* __restrict__ Q, const float* __restrict__ Km,
    const float* __restrict__ V, float* __restrict__ O, int causal)
{
    extern __shared__ float sm[];
    float* Qs = sm;
    float* Ks = sm + ATQ * QS_STRIDE;
    float* Vs = Ks + ATK * QS_STRIDE;

    const int b = blockIdx.z, h = blockIdx.y, qb = blockIdx.x;
    const int tid = threadIdx.x;
    const int wid = tid >> 5, lane = tid & 31;
    const int g = lane >> 2, tg = lane & 3;
    const int qbase = qb * ATQ;
    const int m0 = wid * 16;

    #pragma unroll
    for (int i = 0; i < 8; i++) {
        const int idx = tid + i * 128;
        const int r = idx >> 4;
        const int c = (idx & 15) * 4;
        float4 qv = *(const float4*)(Q + ((size_t)(b * SEQ + qbase + r)) * EMBED + h * DH + c);
        qv.x = to_tf32(qv.x * 0.125f); qv.y = to_tf32(qv.y * 0.125f);
        qv.z = to_tf32(qv.z * 0.125f); qv.w = to_tf32(qv.w * 0.125f);
        *(float4*)(&Qs[r * QS_STRIDE + c]) = qv;
    }
    __syncthreads();

    uint32_t qf[8][4];
    #pragma unroll
    for (int ks = 0; ks < 8; ks++) {
        qf[ks][0] = __float_as_uint(Qs[(m0 + g    ) * QS_STRIDE + ks * 8 + tg    ]);
        qf[ks][1] = __float_as_uint(Qs[(m0 + g + 8) * QS_STRIDE + ks * 8 + tg    ]);
        qf[ks][2] = __float_as_uint(Qs[(m0 + g    ) * QS_STRIDE + ks * 8 + tg + 4]);
        qf[ks][3] = __float_as_uint(Qs[(m0 + g + 8) * QS_STRIDE + ks * 8 + tg + 4]);
    }

    float oacc[8][4];
    #pragma unroll
    for (int ni = 0; ni < 8; ni++)
        #pragma unroll
        for (int r = 0; r < 4; r++) oacc[ni][r] = 0.f;
    float m0r = -1e30f, m1r = -1e30f, l0r = 0.f, l1r = 0.f;

    const int nkt = causal ? (qb + 1) : (SEQ / ATK);
    for (int kt = 0; kt < nkt; kt++) {
        #pragma unroll
        for (int i = 0; i < 8; i++) {
            const int idx = tid + i * 128;
            const int r = idx >> 4;
            const int c = (idx & 15) * 4;
            const size_t go = ((size_t)(b * SEQ + kt * ATK + r)) * EMBED + h * DH + c;
            float4 kk = *(const float4*)(Km + go);
            kk.x = to_tf32(kk.x); kk.y = to_tf32(kk.y);
            kk.z = to_tf32(kk.z); kk.w = to_tf32(kk.w);
            *(float4*)(&Ks[r * QS_STRIDE + c]) = kk;
            float4 vv = *(const float4*)(V + go);
            vv.x = to_tf32(vv.x); vv.y = to_tf32(vv.y);
            vv.z = to_tf32(vv.z); vv.w = to_tf32(vv.w);
            *(float4*)(&Vs[r * VS_STRIDE + c]) = vv;
        }
        __syncthreads();

        float sacc[8][4];
        #pragma unroll
        for (int ni = 0; ni < 8; ni++)
            #pragma unroll
            for (int r = 0; r < 4; r++) sacc[ni][r] = 0.f;
        #pragma unroll
        for (int ks = 0; ks < 8; ks++) {
            #pragma unroll
            for (int ni = 0; ni < 8; ni++) {
                uint32_t bf[2];
                bf[0] = __float_as_uint(Ks[(ni * 8 + g) * QS_STRIDE + ks * 8 + tg    ]);
                bf[1] = __float_as_uint(Ks[(ni * 8 + g) * QS_STRIDE + ks * 8 + tg + 4]);
                mma_tf32(sacc[ni], qf[ks], bf);
            }
        }

        if (causal && kt == qb) {
            const int r0 = qbase + m0 + g, r1 = r0 + 8;
            #pragma unroll
            for (int ni = 0; ni < 8; ni++) {
                const int c0 = kt * ATK + ni * 8 + 2 * tg;
                if (c0     > r0) sacc[ni][0] = -1e30f;
                if (c0 + 1 > r0) sacc[ni][1] = -1e30f;
                if (c0     > r1) sacc[ni][2] = -1e30f;
                if (c0 + 1 > r1) sacc[ni][3] = -1e30f;
            }
        }

        float mx0 = -1e30f, mx1 = -1e30f;
        #pragma unroll
        for (int ni = 0; ni < 8; ni++) {
            mx0 = fmaxf(mx0, fmaxf(sacc[ni][0], sacc[ni][1]));
            mx1 = fmaxf(mx1, fmaxf(sacc[ni][2], sacc[ni][3]));
        }
        mx0 = fmaxf(mx0, __shfl_xor_sync(0xffffffffu, mx0, 1));
        mx0 = fmaxf(mx0, __shfl_xor_sync(0xffffffffu, mx0, 2));
        mx1 = fmaxf(mx1, __shfl_xor_sync(0xffffffffu, mx1, 1));
        mx1 = fmaxf(mx1, __shfl_xor_sync(0xffffffffu, mx1, 2));
        const float mn0 = fmaxf(m0r, mx0);
        const float mn1 = fmaxf(m1r, mx1);
        const float cr0 = __expf(m0r - mn0);
        const float cr1 = __expf(m1r - mn1);
        m0r = mn0; m1r = mn1;

        float ls0 = 0.f, ls1 = 0.f;
        #pragma unroll
        for (int ni = 0; ni < 8; ni++) {
            const float p0 = __expf(sacc[ni][0] - mn0);
            const float p1 = __expf(sacc[ni][1] - mn0);
            const float p2 = __expf(sacc[ni][2] - mn1);
            const float p3 = __expf(sacc[ni][3] - mn1);
            ls0 += p0 + p1; ls1 += p2 + p3;
            *(float2*)(&Qs[(m0 + g    ) * QS_STRIDE + ni * 8 + 2 * tg]) =
                make_float2(to_tf32(p0), to_tf32(p1));
            *(float2*)(&Qs[(m0 + g + 8) * QS_STRIDE + ni * 8 + 2 * tg]) =
                make_float2(to_tf32(p2), to_tf32(p3));
        }
        ls0 += __shfl_xor_sync(0xffffffffu, ls0, 1);
        ls0 += __shfl_xor_sync(0xffffffffu, ls0, 2);
        ls1 += __shfl_xor_sync(0xffffffffu, ls1, 1);
        ls1 += __shfl_xor_sync(0xffffffffu, ls1, 2);
        l0r = l0r * cr0 + ls0;
        l1r = l1r * cr1 + ls1;

        #pragma unroll
        for (int ni = 0; ni < 8; ni++) {
            oacc[ni][0] *= cr0; oacc[ni][1] *= cr0;
            oacc[ni][2] *= cr1; oacc[ni][3] *= cr1;
        }
        __syncwarp();

        #pragma unroll
        for (int ks = 0; ks < 8; ks++) {
            uint32_t af[4];
            af[0] = __float_as_uint(Qs[(m0 + g    ) * QS_STRIDE + ks * 8 + tg    ]);
            af[1] = __float_as_uint(Qs[(m0 + g + 8) * QS_STRIDE + ks * 8 + tg    ]);
            af[2] = __float_as_uint(Qs[(m0 + g    ) * QS_STRIDE + ks * 8 + tg + 4]);
            af[3] = __float_as_uint(Qs[(m0 + g + 8) * QS_STRIDE + ks * 8 + tg + 4]);
            #pragma unroll
            for (int ni = 0; ni < 8; ni++) {
                uint32_t bf[2];
                bf[0] = __float_as_uint(Vs[(ks * 8 + tg    ) * VS_STRIDE + ni * 8 + g]);
                bf[1] = __float_as_uint(Vs[(ks * 8 + tg + 4) * VS_STRIDE + ni * 8 + g]);
                mma_tf32(oacc[ni], af, bf);
            }
        }
        __syncthreads();
    }

    const float inv0 = 1.f / l0r, inv1 = 1.f / l1r;
    #pragma unroll
    for (int ni = 0; ni < 8; ni++) {
        const size_t o0 = ((size_t)(b * SEQ + qbase + m0 + g)) * EMBED + h * DH + ni * 8 + 2 * tg;
        *(float2*)(O + o0)             = make_float2(oacc[ni][0] * inv0, oacc[ni][1] * inv0);
        *(float2*)(O + o0 + 8 * EMBED) = make_float2(oacc[ni][2] * inv1, oacc[ni][3] * inv1);
    }
}

// ---------------- LayerNorm over last dim (512) -----------------------------
__global__ __launch_bounds__(128) void layernorm_k(
    const float* __restrict__ X, const float* __restrict__ G,
    const float* __restrict__ Bt, float* __restrict__ Y)
{
    const int row = blockIdx.x;
    const int t = threadIdx.x;
    const float* xr = X + (size_t)row * EMBED;
    float4 v = *(const float4*)(xr + t * 4);
    float s  = v.x + v.y + v.z + v.w;
    float ss = v.x * v.x + v.y * v.y + v.z * v.z + v.w * v.w;
    #pragma unroll
    for (int o = 16; o > 0; o >>= 1) {
        s  += __shfl_xor_sync(0xffffffffu, s,  o);
        ss += __shfl_xor_sync(0xffffffffu, ss, o);
    }
    __shared__ float sh_s[4], sh_ss[4];
    const int w = t >> 5;
    if ((t & 31) == 0) { sh_s[w] = s; sh_ss[w] = ss; }
    __syncthreads();
    s  = sh_s[0] + sh_s[1] + sh_s[2] + sh_s[3];
    ss = sh_ss[0] + sh_ss[1] + sh_ss[2] + sh_ss[3];
    const float mean = s * (1.f / EMBED);
    const float var  = ss * (1.f / EMBED) - mean * mean;
    const float rstd = rsqrtf(var + 1e-5f);
    float4 gg = *(const float4*)(G  + t * 4);
    float4 bb = *(const float4*)(Bt + t * 4);
    float4 o;
    o.x = (v.x - mean) * rstd * gg.x + bb.x;
    o.y = (v.y - mean) * rstd * gg.y + bb.y;
    o.z = (v.z - mean) * rstd * gg.z + bb.z;
    o.w = (v.w - mean) * rstd * gg.w + bb.w;
    *(float4*)(Y + (size_t)row * EMBED + t * 4) = o;
}

// ---------------- launch --------------------------------------------------
extern "C" void kernel_launch(void* const* d_in, const int* in_sizes, int n_in,
                              void* d_out, int out_size)
{
    const float* x     = (const float*)d_in[0];
    const float* enc   = (const float*)d_in[1];
    const float* sa_wq = (const float*)d_in[2];
    const float* sa_bq = (const float*)d_in[3];
    const float* sa_wk = (const float*)d_in[4];
    const float* sa_bk = (const float*)d_in[5];
    const float* sa_wv = (const float*)d_in[6];
    const float* sa_bv = (const float*)d_in[7];
    const float* sa_wo = (const float*)d_in[8];
    const float* sa_bo = (const float*)d_in[9];
    const float* ca_wq = (const float*)d_in[10];
    const float* ca_bq = (const float*)d_in[11];
    const float* ca_wk = (const float*)d_in[12];
    const float* ca_bk = (const float*)d_in[13];
    const float* ca_wv = (const float*)d_in[14];
    const float* ca_bv = (const float*)d_in[15];
    const float* ca_wo = (const float*)d_in[16];
    const float* ca_bo = (const float*)d_in[17];
    const float* ln1_g = (const float*)d_in[18];
    const float* ln1_b = (const float*)d_in[19];
    const float* ln2_g = (const float*)d_in[20];
    const float* ln2_b = (const float*)d_in[21];
    const float* ln3_g = (const float*)d_in[22];
    const float* ln3_b = (const float*)d_in[23];
    const float* ff_w1 = (const float*)d_in[24];
    const float* ff_b1 = (const float*)d_in[25];
    const float* ff_w2 = (const float*)d_in[26];
    const float* ff_b2 = (const float*)d_in[27];
    float* out = (float*)d_out;

    float *q, *k, *v, *attn, *xb, *hb;
    cudaGetSymbolAddress((void**)&q,    g_q);
    cudaGetSymbolAddress((void**)&k,    g_k);
    cudaGetSymbolAddress((void**)&v,    g_v);
    cudaGetSymbolAddress((void**)&attn, g_attn);
    cudaGetSymbolAddress((void**)&xb,   g_x);
    cudaGetSymbolAddress((void**)&hb,   g_h);

    static int fa_attr_set = 0;
    if (!fa_attr_set) {
        cudaFuncSetAttribute(flash_mma,
                             cudaFuncAttributeMaxDynamicSharedMemorySize, FA_SMEM);
        fa_attr_set = 1;
    }

    dim3 g512(EMBED / GBN, ROWS / GBM);      // (8, 32)
    dim3 gqkv(EMBED / GBN, ROWS / GBM, 3);   // (8, 32, 3)
    dim3 gff (FF    / GBN, ROWS / GBM);      // (32, 32)
    dim3 gfl (SEQ / ATQ, NH, BATCH);         // (32, 8, 2)

    // ---- self attention (causal) ----
    tgemm_qkv<<<gqkv, 256>>>(x, x, sa_wq, sa_bq, sa_wk, sa_bk, sa_wv, sa_bv, q, k, v);
    flash_mma<<<gfl, 128, FA_SMEM>>>(q, k, v, attn, 1);
    tgemm_ep<<<g512, 256>>>(attn, sa_wo, sa_bo, x, xb, ROWS, EMBED, EMBED, EP_RES);
    layernorm_k<<<ROWS, 128>>>(xb, ln1_g, ln1_b, xb);

    // ---- cross attention ----
    tgemm_qkv<<<gqkv, 256>>>(xb, enc, ca_wq, ca_bq, ca_wk, ca_bk, ca_wv, ca_bv, q, k, v);
    flash_mma<<<gfl, 128, FA_SMEM>>>(q, k, v, attn, 0);
    tgemm_ep<<<g512, 256>>>(attn, ca_wo, ca_bo, xb, xb, ROWS, EMBED, EMBED, EP_RES);
    layernorm_k<<<ROWS, 128>>>(xb, ln2_g, ln2_b, xb);

    // ---- feed-forward ----
    tgemm_ep<<<gff, 256>>>(xb, ff_w1, ff_b1, nullptr, hb, ROWS, FF, EMBED, EP_GELU);
    tgemm_ep<<<g512, 256>>>(hb, ff_w2, ff_b2, xb, xb, ROWS, EMBED, FF, EP_RES);
    layernorm_k<<<ROWS, 128>>>(xb, ln3_g, ln3_b, out);
}

// round 8
// speedup vs baseline: 7.0477x; 1.0926x over previous
#include <cuda_runtime.h>
#include <cuda_fp16.h>
#include <math.h>
#include <stdint.h>

#define EMBED 512
#define NH    8
#define DH    64
#define BATCH 2
#define SEQ   2048
#define ROWS  (BATCH*SEQ)   // 4096
#define FF    2048

// ---------------- scratch (no allocation allowed) ----------------
__device__ float g_q[ROWS*EMBED];
__device__ float g_k[ROWS*EMBED];
__device__ float g_v[ROWS*EMBED];
__device__ float g_attn[ROWS*EMBED];
__device__ float g_x[ROWS*EMBED];
__device__ float g_h[ROWS*FF];
// fp16 transposed weights: 8x(512x512) + 2x(512x2048)
#define WSQ (512*512)
#define WFF (512*2048)
__device__ __half g_wh[8*WSQ + 2*WFF];

#define EP_BIAS 0
#define EP_RES  1
#define EP_GELU 2

__device__ __forceinline__ float to_tf32(float x) {
    float y;
    asm("cvt.rna.tf32.f32 %0, %1;" : "=f"(y) : "f"(x));
    return y;
}

__device__ __forceinline__ void mma_tf32(
    float c[4], const uint32_t a[4], const uint32_t b[2])
{
    asm volatile(
        "mma.sync.aligned.m16n8k8.row.col.f32.tf32.tf32.f32 "
        "{%0,%1,%2,%3}, {%4,%5,%6,%7}, {%8,%9}, {%0,%1,%2,%3};"
        : "+f"(c[0]), "+f"(c[1]), "+f"(c[2]), "+f"(c[3])
        : "r"(a[0]), "r"(a[1]), "r"(a[2]), "r"(a[3]), "r"(b[0]), "r"(b[1]));
}

__device__ __forceinline__ void mma_f16(
    float c[4], const uint32_t a[4], const uint32_t b[2])
{
    asm volatile(
        "mma.sync.aligned.m16n8k16.row.col.f32.f16.f16.f32 "
        "{%0,%1,%2,%3}, {%4,%5,%6,%7}, {%8,%9}, {%0,%1,%2,%3};"
        : "+f"(c[0]), "+f"(c[1]), "+f"(c[2]), "+f"(c[3])
        : "r"(a[0]), "r"(a[1]), "r"(a[2]), "r"(a[3]), "r"(b[0]), "r"(b[1]));
}

__device__ __forceinline__ void cpasync16(void* sptr, const void* gptr) {
    uint32_t s = (uint32_t)__cvta_generic_to_shared(sptr);
    asm volatile("cp.async.ca.shared.global [%0], [%1], 16;\n" :: "r"(s), "l"(gptr));
}
__device__ __forceinline__ void cpasync_commit() {
    asm volatile("cp.async.commit_group;\n" ::: "memory");
}
template <int N>
__device__ __forceinline__ void cpasync_wait() {
    asm volatile("cp.async.wait_group %0;\n" :: "n"(N) : "memory");
}

// ---------------- weight transpose+convert: W[K][N] fp32 -> Wt[N][K] fp16 ----
__global__ __launch_bounds__(256) void wconv(
    const float* __restrict__ W, __half* __restrict__ Wt, int K, int N)
{
    __shared__ float tile[32][33];
    const int n0 = blockIdx.x * 32, k0 = blockIdx.y * 32;
    const int tx = threadIdx.x & 31, ty = threadIdx.x >> 5;   // 32x8
    #pragma unroll
    for (int j = 0; j < 4; j++)
        tile[ty + j * 8][tx] = W[(size_t)(k0 + ty + j * 8) * N + n0 + tx];
    __syncthreads();
    #pragma unroll
    for (int j = 0; j < 4; j++)
        Wt[(size_t)(n0 + ty + j * 8) * K + k0 + tx] =
            __float2half_rn(tile[tx][ty + j * 8]);
}

// ================= fp16 tensor-core GEMM ====================================
// C[M,N] = A[M,K](fp32) @ W[K,N] via Wt[N][K] fp16, fp32 accum.
// Block tile 128x64x32, 256 threads = 8 warps (4x2), warp tile 32x32.
#define GBM 128
#define GBN 64
#define GBKH 32          // K elements (halves) per tile
#define AS_W 20          // uint32 words per A row (16 data + 4 pad)
#define BS_W 20

__device__ __forceinline__ void hgemm_body(
    const float* __restrict__ A, const __half* __restrict__ Wt,
    const float* __restrict__ bias, const float* __restrict__ R,
    float* __restrict__ C, int M, int N, int K, int ep,
    int bm, int bn)
{
    __shared__ uint32_t As[2][GBM * AS_W];   // 2 x 10240 B
    __shared__ uint32_t Bs[2][GBN * BS_W];   // 2 x  5120 B

    const int tid  = threadIdx.x;
    const int wid  = tid >> 5;
    const int lane = tid & 31;
    const int g    = lane >> 2;
    const int tg   = lane & 3;
    const int warpM = (wid >> 1) * 32;   // 0,32,64,96
    const int warpN = (wid & 1) * 32;    // 0,32

    // A load coords: thread covers 16 contiguous floats of one row
    const int aRow  = tid >> 1;          // 0..127
    const int aPart = tid & 1;           // halves of 32-float row
    // B cp.async coords: one 16B chunk per thread
    const int bN  = tid >> 2;            // 0..63
    const int bCh = tid & 3;             // 0..3

    float c[2][4][4];
    #pragma unroll
    for (int mi = 0; mi < 2; mi++)
        #pragma unroll
        for (int ni = 0; ni < 4; ni++)
            #pragma unroll
            for (int r = 0; r < 4; r++) c[mi][ni][r] = 0.f;

    const int nkb = K / GBKH;

    // prologue: A tile0 -> regs, B tile0 -> cp.async
    float4 areg[4];
    {
        const float* ap = A + (size_t)(bm + aRow) * K + aPart * 16;
        #pragma unroll
        for (int i = 0; i < 4; i++) areg[i] = *(const float4*)(ap + 4 * i);
        cpasync16(&Bs[0][bN * BS_W + bCh * 4],
                  Wt + (size_t)(bn + bN) * K + bCh * 8);
        cpasync_commit();
    }

    for (int kb = 0; kb < nkb; kb++) {
        const int cur = kb & 1;
        // convert + store A regs into As[cur]
        {
            uint32_t w[8];
            #pragma unroll
            for (int i = 0; i < 4; i++) {
                half2 lo = __float22half2_rn(make_float2(areg[i].x, areg[i].y));
                half2 hi = __float22half2_rn(make_float2(areg[i].z, areg[i].w));
                w[2 * i]     = *(uint32_t*)&lo;
                w[2 * i + 1] = *(uint32_t*)&hi;
            }
            uint32_t* dst = &As[cur][aRow * AS_W + aPart * 8];
            *(uint4*)(dst)     = make_uint4(w[0], w[1], w[2], w[3]);
            *(uint4*)(dst + 4) = make_uint4(w[4], w[5], w[6], w[7]);
        }
        if (kb + 1 < nkb) {
            const int nxt = cur ^ 1;
            const int k0 = (kb + 1) * GBKH;
            const float* ap = A + (size_t)(bm + aRow) * K + k0 + aPart * 16;
            #pragma unroll
            for (int i = 0; i < 4; i++) areg[i] = *(const float4*)(ap + 4 * i);
            cpasync16(&Bs[nxt][bN * BS_W + bCh * 4],
                      Wt + (size_t)(bn + bN) * K + k0 + bCh * 8);
            cpasync_commit();
            cpasync_wait<1>();
        } else {
            cpasync_wait<0>();
        }
        __syncthreads();

        const uint32_t* as = As[cur];
        const uint32_t* bs = Bs[cur];
        #pragma unroll
        for (int kw = 0; kw < 16; kw += 8) {      // two k16 steps
            uint32_t af[2][4], bf[4][2];
            #pragma unroll
            for (int mi = 0; mi < 2; mi++) {
                const int m0 = warpM + mi * 16;
                af[mi][0] = as[(m0 + g    ) * AS_W + kw + tg    ];
                af[mi][1] = as[(m0 + g + 8) * AS_W + kw + tg    ];
                af[mi][2] = as[(m0 + g    ) * AS_W + kw + tg + 4];
                af[mi][3] = as[(m0 + g + 8) * AS_W + kw + tg + 4];
            }
            #pragma unroll
            for (int ni = 0; ni < 4; ni++) {
                const int n0 = warpN + ni * 8 + g;
                bf[ni][0] = bs[n0 * BS_W + kw + tg    ];
                bf[ni][1] = bs[n0 * BS_W + kw + tg + 4];
            }
            #pragma unroll
            for (int mi = 0; mi < 2; mi++)
                #pragma unroll
                for (int ni = 0; ni < 4; ni++)
                    mma_f16(c[mi][ni], af[mi], bf[ni]);
        }
        __syncthreads();
    }

    // ---- epilogue ----
    #pragma unroll
    for (int mi = 0; mi < 2; mi++) {
        #pragma unroll
        for (int ni = 0; ni < 4; ni++) {
            const int col = bn + warpN + ni * 8 + tg * 2;
            const float b0 = bias[col], b1 = bias[col + 1];
            #pragma unroll
            for (int h = 0; h < 2; h++) {
                const int row = bm + warpM + mi * 16 + g + h * 8;
                float v0 = c[mi][ni][2 * h + 0] + b0;
                float v1 = c[mi][ni][2 * h + 1] + b1;
                if (ep == EP_RES) {
                    const float2 rr = *(const float2*)(R + (size_t)row * N + col);
                    v0 += rr.x; v1 += rr.y;
                } else if (ep == EP_GELU) {
                    v0 = 0.5f * v0 * (1.0f + erff(v0 * 0.70710678118654752f));
                    v1 = 0.5f * v1 * (1.0f + erff(v1 * 0.70710678118654752f));
                }
                *(float2*)(C + (size_t)row * N + col) = make_float2(v0, v1);
            }
        }
    }
}

__global__ __launch_bounds__(256) void hgemm_ep(
    const float* __restrict__ A, const __half* __restrict__ Wt,
    const float* __restrict__ bias, const float* __restrict__ R,
    float* __restrict__ C, int M, int N, int K, int ep)
{
    hgemm_body(A, Wt, bias, R, C, M, N, K, ep,
               blockIdx.y * GBM, blockIdx.x * GBN);
}

__global__ __launch_bounds__(256) void hgemm_qkv(
    const float* __restrict__ Aq, const float* __restrict__ Akv,
    const __half* __restrict__ Wq, const float* __restrict__ bq,
    const __half* __restrict__ Wk, const float* __restrict__ bk,
    const __half* __restrict__ Wv, const float* __restrict__ bv,
    float* __restrict__ Cq, float* __restrict__ Ck, float* __restrict__ Cv)
{
    const int z = blockIdx.z;
    const float* A = (z == 0) ? Aq : Akv;
    const __half* W = (z == 0) ? Wq : (z == 1) ? Wk : Wv;
    const float* bia = (z == 0) ? bq : (z == 1) ? bk : bv;
    float* C = (z == 0) ? Cq : (z == 1) ? Ck : Cv;
    hgemm_body(A, W, bia, nullptr, C, ROWS, EMBED, EMBED, EP_BIAS,
               blockIdx.y * GBM, blockIdx.x * GBN);
}

// ================= tf32 tensor-core flash attention (unchanged R6/R7) =======
#define ATQ 64
#define ATK 64
#define QS_STRIDE 68
#define VS_STRIDE 72
#define FA_SMEM ((2*ATQ*QS_STRIDE + ATK*VS_STRIDE) * 4)   // 53248 bytes

__global__ __launch_bounds__(128) void flash_mma(
    const float* __restrict__ Q, const float* __restrict__ Km,
    const float* __restrict__ V, float* __restrict__ O, int causal)
{
    extern __shared__ float sm[];
    float* Qs = sm;
    float* Ks = sm + ATQ * QS_STRIDE;
    float* Vs = Ks + ATK * QS_STRIDE;

    const int b = blockIdx.z, h = blockIdx.y, qb = blockIdx.x;
    const int tid = threadIdx.x;
    const int wid = tid >> 5, lane = tid & 31;
    const int g = lane >> 2, tg = lane & 3;
    const int qbase = qb * ATQ;
    const int m0 = wid * 16;

    #pragma unroll
    for (int i = 0; i < 8; i++) {
        const int idx = tid + i * 128;
        const int r = idx >> 4;
        const int c = (idx & 15) * 4;
        float4 qv = *(const float4*)(Q + ((size_t)(b * SEQ + qbase + r)) * EMBED + h * DH + c);
        qv.x = to_tf32(qv.x * 0.125f); qv.y = to_tf32(qv.y * 0.125f);
        qv.z = to_tf32(qv.z * 0.125f); qv.w = to_tf32(qv.w * 0.125f);
        *(float4*)(&Qs[r * QS_STRIDE + c]) = qv;
    }
    __syncthreads();

    uint32_t qf[8][4];
    #pragma unroll
    for (int ks = 0; ks < 8; ks++) {
        qf[ks][0] = __float_as_uint(Qs[(m0 + g    ) * QS_STRIDE + ks * 8 + tg    ]);
        qf[ks][1] = __float_as_uint(Qs[(m0 + g + 8) * QS_STRIDE + ks * 8 + tg    ]);
        qf[ks][2] = __float_as_uint(Qs[(m0 + g    ) * QS_STRIDE + ks * 8 + tg + 4]);
        qf[ks][3] = __float_as_uint(Qs[(m0 + g + 8) * QS_STRIDE + ks * 8 + tg + 4]);
    }

    float oacc[8][4];
    #pragma unroll
    for (int ni = 0; ni < 8; ni++)
        #pragma unroll
        for (int r = 0; r < 4; r++) oacc[ni][r] = 0.f;
    float m0r = -1e30f, m1r = -1e30f, l0r = 0.f, l1r = 0.f;

    const int nkt = causal ? (qb + 1) : (SEQ / ATK);
    for (int kt = 0; kt < nkt; kt++) {
        #pragma unroll
        for (int i = 0; i < 8; i++) {
            const int idx = tid + i * 128;
            const int r = idx >> 4;
            const int c = (idx & 15) * 4;
            const size_t go = ((size_t)(b * SEQ + kt * ATK + r)) * EMBED + h * DH + c;
            float4 kk = *(const float4*)(Km + go);
            kk.x = to_tf32(kk.x); kk.y = to_tf32(kk.y);
            kk.z = to_tf32(kk.z); kk.w = to_tf32(kk.w);
            *(float4*)(&Ks[r * QS_STRIDE + c]) = kk;
            float4 vv = *(const float4*)(V + go);
            vv.x = to_tf32(vv.x); vv.y = to_tf32(vv.y);
            vv.z = to_tf32(vv.z); vv.w = to_tf32(vv.w);
            *(float4*)(&Vs[r * VS_STRIDE + c]) = vv;
        }
        __syncthreads();

        float sacc[8][4];
        #pragma unroll
        for (int ni = 0; ni < 8; ni++)
            #pragma unroll
            for (int r = 0; r < 4; r++) sacc[ni][r] = 0.f;
        #pragma unroll
        for (int ks = 0; ks < 8; ks++) {
            #pragma unroll
            for (int ni = 0; ni < 8; ni++) {
                uint32_t bf[2];
                bf[0] = __float_as_uint(Ks[(ni * 8 + g) * QS_STRIDE + ks * 8 + tg    ]);
                bf[1] = __float_as_uint(Ks[(ni * 8 + g) * QS_STRIDE + ks * 8 + tg + 4]);
                mma_tf32(sacc[ni], qf[ks], bf);
            }
        }

        if (causal && kt == qb) {
            const int r0 = qbase + m0 + g, r1 = r0 + 8;
            #pragma unroll
            for (int ni = 0; ni < 8; ni++) {
                const int c0 = kt * ATK + ni * 8 + 2 * tg;
                if (c0     > r0) sacc[ni][0] = -1e30f;
                if (c0 + 1 > r0) sacc[ni][1] = -1e30f;
                if (c0     > r1) sacc[ni][2] = -1e30f;
                if (c0 + 1 > r1) sacc[ni][3] = -1e30f;
            }
        }

        float mx0 = -1e30f, mx1 = -1e30f;
        #pragma unroll
        for (int ni = 0; ni < 8; ni++) {
            mx0 = fmaxf(mx0, fmaxf(sacc[ni][0], sacc[ni][1]));
            mx1 = fmaxf(mx1, fmaxf(sacc[ni][2], sacc[ni][3]));
        }
        mx0 = fmaxf(mx0, __shfl_xor_sync(0xffffffffu, mx0, 1));
        mx0 = fmaxf(mx0, __shfl_xor_sync(0xffffffffu, mx0, 2));
        mx1 = fmaxf(mx1, __shfl_xor_sync(0xffffffffu, mx1, 1));
        mx1 = fmaxf(mx1, __shfl_xor_sync(0xffffffffu, mx1, 2));
        const float mn0 = fmaxf(m0r, mx0);
        const float mn1 = fmaxf(m1r, mx1);
        const float cr0 = __expf(m0r - mn0);
        const float cr1 = __expf(m1r - mn1);
        m0r = mn0; m1r = mn1;

        float ls0 = 0.f, ls1 = 0.f;
        #pragma unroll
        for (int ni = 0; ni < 8; ni++) {
            const float p0 = __expf(sacc[ni][0] - mn0);
            const float p1 = __expf(sacc[ni][1] - mn0);
            const float p2 = __expf(sacc[ni][2] - mn1);
            const float p3 = __expf(sacc[ni][3] - mn1);
            ls0 += p0 + p1; ls1 += p2 + p3;
            *(float2*)(&Qs[(m0 + g    ) * QS_STRIDE + ni * 8 + 2 * tg]) =
                make_float2(to_tf32(p0), to_tf32(p1));
            *(float2*)(&Qs[(m0 + g + 8) * QS_STRIDE + ni * 8 + 2 * tg]) =
                make_float2(to_tf32(p2), to_tf32(p3));
        }
        ls0 += __shfl_xor_sync(0xffffffffu, ls0, 1);
        ls0 += __shfl_xor_sync(0xffffffffu, ls0, 2);
        ls1 += __shfl_xor_sync(0xffffffffu, ls1, 1);
        ls1 += __shfl_xor_sync(0xffffffffu, ls1, 2);
        l0r = l0r * cr0 + ls0;
        l1r = l1r * cr1 + ls1;

        #pragma unroll
        for (int ni = 0; ni < 8; ni++) {
            oacc[ni][0] *= cr0; oacc[ni][1] *= cr0;
            oacc[ni][2] *= cr1; oacc[ni][3] *= cr1;
        }
        __syncwarp();

        #pragma unroll
        for (int ks = 0; ks < 8; ks++) {
            uint32_t af[4];
            af[0] = __float_as_uint(Qs[(m0 + g    ) * QS_STRIDE + ks * 8 + tg    ]);
            af[1] = __float_as_uint(Qs[(m0 + g + 8) * QS_STRIDE + ks * 8 + tg    ]);
            af[2] = __float_as_uint(Qs[(m0 + g    ) * QS_STRIDE + ks * 8 + tg + 4]);
            af[3] = __float_as_uint(Qs[(m0 + g + 8) * QS_STRIDE + ks * 8 + tg + 4]);
            #pragma unroll
            for (int ni = 0; ni < 8; ni++) {
                uint32_t bf[2];
                bf[0] = __float_as_uint(Vs[(ks * 8 + tg    ) * VS_STRIDE + ni * 8 + g]);
                bf[1] = __float_as_uint(Vs[(ks * 8 + tg + 4) * VS_STRIDE + ni * 8 + g]);
                mma_tf32(oacc[ni], af, bf);
            }
        }
        __syncthreads();
    }

    const float inv0 = 1.f / l0r, inv1 = 1.f / l1r;
    #pragma unroll
    for (int ni = 0; ni < 8; ni++) {
        const size_t o0 = ((size_t)(b * SEQ + qbase + m0 + g)) * EMBED + h * DH + ni * 8 + 2 * tg;
        *(float2*)(O + o0)             = make_float2(oacc[ni][0] * inv0, oacc[ni][1] * inv0);
        *(float2*)(O + o0 + 8 * EMBED) = make_float2(oacc[ni][2] * inv1, oacc[ni][3] * inv1);
    }
}

// ---------------- LayerNorm over last dim (512) -----------------------------
__global__ __launch_bounds__(128) void layernorm_k(
    const float* __restrict__ X, const float* __restrict__ G,
    const float* __restrict__ Bt, float* __restrict__ Y)
{
    const int row = blockIdx.x;
    const int t = threadIdx.x;
    const float* xr = X + (size_t)row * EMBED;
    float4 v = *(const float4*)(xr + t * 4);
    float s  = v.x + v.y + v.z + v.w;
    float ss = v.x * v.x + v.y * v.y + v.z * v.z + v.w * v.w;
    #pragma unroll
    for (int o = 16; o > 0; o >>= 1) {
        s  += __shfl_xor_sync(0xffffffffu, s,  o);
        ss += __shfl_xor_sync(0xffffffffu, ss, o);
    }
    __shared__ float sh_s[4], sh_ss[4];
    const int w = t >> 5;
    if ((t & 31) == 0) { sh_s[w] = s; sh_ss[w] = ss; }
    __syncthreads();
    s  = sh_s[0] + sh_s[1] + sh_s[2] + sh_s[3];
    ss = sh_ss[0] + sh_ss[1] + sh_ss[2] + sh_ss[3];
    const float mean = s * (1.f / EMBED);
    const float var  = ss * (1.f / EMBED) - mean * mean;
    const float rstd = rsqrtf(var + 1e-5f);
    float4 gg = *(const float4*)(G  + t * 4);
    float4 bb = *(const float4*)(Bt + t * 4);
    float4 o;
    o.x = (v.x - mean) * rstd * gg.x + bb.x;
    o.y = (v.y - mean) * rstd * gg.y + bb.y;
    o.z = (v.z - mean) * rstd * gg.z + bb.z;
    o.w = (v.w - mean) * rstd * gg.w + bb.w;
    *(float4*)(Y + (size_t)row * EMBED + t * 4) = o;
}

// ---------------- launch --------------------------------------------------
extern "C" void kernel_launch(void* const* d_in, const int* in_sizes, int n_in,
                              void* d_out, int out_size)
{
    const float* x     = (const float*)d_in[0];
    const float* enc   = (const float*)d_in[1];
    const float* sa_wq = (const float*)d_in[2];
    const float* sa_bq = (const float*)d_in[3];
    const float* sa_wk = (const float*)d_in[4];
    const float* sa_bk = (const float*)d_in[5];
    const float* sa_wv = (const float*)d_in[6];
    const float* sa_bv = (const float*)d_in[7];
    const float* sa_wo = (const float*)d_in[8];
    const float* sa_bo = (const float*)d_in[9];
    const float* ca_wq = (const float*)d_in[10];
    const float* ca_bq = (const float*)d_in[11];
    const float* ca_wk = (const float*)d_in[12];
    const float* ca_bk = (const float*)d_in[13];
    const float* ca_wv = (const float*)d_in[14];
    const float* ca_bv = (const float*)d_in[15];
    const float* ca_wo = (const float*)d_in[16];
    const float* ca_bo = (const float*)d_in[17];
    const float* ln1_g = (const float*)d_in[18];
    const float* ln1_b = (const float*)d_in[19];
    const float* ln2_g = (const float*)d_in[20];
    const float* ln2_b = (const float*)d_in[21];
    const float* ln3_g = (const float*)d_in[22];
    const float* ln3_b = (const float*)d_in[23];
    const float* ff_w1 = (const float*)d_in[24];
    const float* ff_b1 = (const float*)d_in[25];
    const float* ff_w2 = (const float*)d_in[26];
    const float* ff_b2 = (const float*)d_in[27];
    float* out = (float*)d_out;

    float *q, *k, *v, *attn, *xb, *hb;
    __half* wh;
    cudaGetSymbolAddress((void**)&q,    g_q);
    cudaGetSymbolAddress((void**)&k,    g_k);
    cudaGetSymbolAddress((void**)&v,    g_v);
    cudaGetSymbolAddress((void**)&attn, g_attn);
    cudaGetSymbolAddress((void**)&xb,   g_x);
    cudaGetSymbolAddress((void**)&hb,   g_h);
    cudaGetSymbolAddress((void**)&wh,   g_wh);

    __half* w_saq = wh + 0 * WSQ;
    __half* w_sak = wh + 1 * WSQ;
    __half* w_sav = wh + 2 * WSQ;
    __half* w_sao = wh + 3 * WSQ;
    __half* w_caq = wh + 4 * WSQ;
    __half* w_cak = wh + 5 * WSQ;
    __half* w_cav = wh + 6 * WSQ;
    __half* w_cao = wh + 7 * WSQ;
    __half* w_ff1 = wh + 8 * WSQ;
    __half* w_ff2 = wh + 8 * WSQ + WFF;

    static int fa_attr_set = 0;
    if (!fa_attr_set) {
        cudaFuncSetAttribute(flash_mma,
                             cudaFuncAttributeMaxDynamicSharedMemorySize, FA_SMEM);
        fa_attr_set = 1;
    }

    // ---- weight transpose+convert (fp32 [K][N] -> fp16 [N][K]) ----
    dim3 gsq(16, 16);
    wconv<<<gsq, 256>>>(sa_wq, w_saq, 512, 512);
    wconv<<<gsq, 256>>>(sa_wk, w_sak, 512, 512);
    wconv<<<gsq, 256>>>(sa_wv, w_sav, 512, 512);
    wconv<<<gsq, 256>>>(sa_wo, w_sao, 512, 512);
    wconv<<<gsq, 256>>>(ca_wq, w_caq, 512, 512);
    wconv<<<gsq, 256>>>(ca_wk, w_cak, 512, 512);
    wconv<<<gsq, 256>>>(ca_wv, w_cav, 512, 512);
    wconv<<<gsq, 256>>>(ca_wo, w_cao, 512, 512);
    wconv<<<dim3(64, 16), 256>>>(ff_w1, w_ff1, 512, FF);
    wconv<<<dim3(16, 64), 256>>>(ff_w2, w_ff2, FF, 512);

    dim3 g512(EMBED / GBN, ROWS / GBM);      // (8, 32)
    dim3 gqkv(EMBED / GBN, ROWS / GBM, 3);   // (8, 32, 3)
    dim3 gff (FF    / GBN, ROWS / GBM);      // (32, 32)
    dim3 gfl (SEQ / ATQ, NH, BATCH);         // (32, 8, 2)

    // ---- self attention (causal) ----
    hgemm_qkv<<<gqkv, 256>>>(x, x, w_saq, sa_bq, w_sak, sa_bk, w_sav, sa_bv, q, k, v);
    flash_mma<<<gfl, 128, FA_SMEM>>>(q, k, v, attn, 1);
    hgemm_ep<<<g512, 256>>>(attn, w_sao, sa_bo, x, xb, ROWS, EMBED, EMBED, EP_RES);
    layernorm_k<<<ROWS, 128>>>(xb, ln1_g, ln1_b, xb);

    // ---- cross attention ----
    hgemm_qkv<<<gqkv, 256>>>(xb, enc, w_caq, ca_bq, w_cak, ca_bk, w_cav, ca_bv, q, k, v);
    flash_mma<<<gfl, 128, FA_SMEM>>>(q, k, v, attn, 0);
    hgemm_ep<<<g512, 256>>>(attn, w_cao, ca_bo, xb, xb, ROWS, EMBED, EMBED, EP_RES);
    layernorm_k<<<ROWS, 128>>>(xb, ln2_g, ln2_b, xb);

    // ---- feed-forward ----
    hgemm_ep<<<gff, 256>>>(xb, w_ff1, ff_b1, nullptr, hb, ROWS, FF, EMBED, EP_GELU);
    hgemm_ep<<<g512, 256>>>(hb, w_ff2, ff_b2, xb, xb, ROWS, EMBED, FF, EP_RES);
    layernorm_k<<<ROWS, 128>>>(xb, ln3_g, ln3_b, out);
}

// round 9
// speedup vs baseline: 8.7751x; 1.2451x over previous
#include <cuda_runtime.h>
#include <cuda_fp16.h>
#include <math.h>
#include <stdint.h>

#define EMBED 512
#define NH    8
#define DH    64
#define BATCH 2
#define SEQ   2048
#define ROWS  (BATCH*SEQ)   // 4096
#define FF    2048

// ---------------- scratch (no allocation allowed) ----------------
__device__ float g_q[ROWS*EMBED];
__device__ float g_k[ROWS*EMBED];
__device__ float g_v[ROWS*EMBED];
__device__ float g_attn[ROWS*EMBED];
__device__ float g_x[ROWS*EMBED];
__device__ float g_h[ROWS*FF];
// fp16 transposed weights: 8x(512x512) + 2x(512x2048)
#define WSQ (512*512)
#define WFF (512*2048)
__device__ __half g_wh[8*WSQ + 2*WFF];

#define EP_BIAS 0
#define EP_RES  1
#define EP_GELU 2

__device__ __forceinline__ void mma_f16(
    float c[4], const uint32_t a[4], const uint32_t b[2])
{
    asm volatile(
        "mma.sync.aligned.m16n8k16.row.col.f32.f16.f16.f32 "
        "{%0,%1,%2,%3}, {%4,%5,%6,%7}, {%8,%9}, {%0,%1,%2,%3};"
        : "+f"(c[0]), "+f"(c[1]), "+f"(c[2]), "+f"(c[3])
        : "r"(a[0]), "r"(a[1]), "r"(a[2]), "r"(a[3]), "r"(b[0]), "r"(b[1]));
}

__device__ __forceinline__ void cpasync16(void* sptr, const void* gptr) {
    uint32_t s = (uint32_t)__cvta_generic_to_shared(sptr);
    asm volatile("cp.async.ca.shared.global [%0], [%1], 16;\n" :: "r"(s), "l"(gptr));
}
__device__ __forceinline__ void cpasync_commit() {
    asm volatile("cp.async.commit_group;\n" ::: "memory");
}
template <int N>
__device__ __forceinline__ void cpasync_wait() {
    asm volatile("cp.async.wait_group %0;\n" :: "n"(N) : "memory");
}

__device__ __forceinline__ uint32_t packh2(float a, float b) {
    half2 h = __floats2half2_rn(a, b);
    return *(uint32_t*)&h;
}

// ---------------- ALL weight transposes in ONE launch -----------------------
// W[K][N] fp32 -> Wt[N][K] fp16. 4096 tiles total.
__global__ __launch_bounds__(256) void wconv_all(
    const float* s0, const float* s1, const float* s2, const float* s3,
    const float* s4, const float* s5, const float* s6, const float* s7,
    const float* s8, const float* s9, __half* __restrict__ wh)
{
    __shared__ float tile[32][33];
    const int id = blockIdx.x;
    const float* W; __half* Wt; int K, N, bx, by;
    if (id < 2048) {
        const float* tab[8] = {s0, s1, s2, s3, s4, s5, s6, s7};
        const int wi = id >> 8, rem = id & 255;
        W = tab[wi]; Wt = wh + (size_t)wi * WSQ;
        K = 512; N = 512; bx = rem & 15; by = rem >> 4;
    } else if (id < 3072) {
        const int rem = id - 2048;
        W = s8; Wt = wh + (size_t)8 * WSQ;
        K = 512; N = 2048; bx = rem & 63; by = rem >> 6;
    } else {
        const int rem = id - 3072;
        W = s9; Wt = wh + (size_t)8 * WSQ + WFF;
        K = 2048; N = 512; bx = rem & 15; by = rem >> 4;
    }
    const int n0 = bx * 32, k0 = by * 32;
    const int tx = threadIdx.x & 31, ty = threadIdx.x >> 5;   // 32x8
    #pragma unroll
    for (int j = 0; j < 4; j++)
        tile[ty + j * 8][tx] = W[(size_t)(k0 + ty + j * 8) * N + n0 + tx];
    __syncthreads();
    #pragma unroll
    for (int j = 0; j < 4; j++)
        Wt[(size_t)(n0 + ty + j * 8) * K + k0 + tx] =
            __float2half_rn(tile[tx][ty + j * 8]);
}

// ================= fp16 tensor-core GEMM (unchanged from R8) ================
#define GBM 128
#define GBN 64
#define GBKH 32
#define AS_W 20
#define BS_W 20

__device__ __forceinline__ void hgemm_body(
    const float* __restrict__ A, const __half* __restrict__ Wt,
    const float* __restrict__ bias, const float* __restrict__ R,
    float* __restrict__ C, int M, int N, int K, int ep,
    int bm, int bn)
{
    __shared__ uint32_t As[2][GBM * AS_W];
    __shared__ uint32_t Bs[2][GBN * BS_W];

    const int tid  = threadIdx.x;
    const int wid  = tid >> 5;
    const int lane = tid & 31;
    const int g    = lane >> 2;
    const int tg   = lane & 3;
    const int warpM = (wid >> 1) * 32;
    const int warpN = (wid & 1) * 32;

    const int aRow  = tid >> 1;
    const int aPart = tid & 1;
    const int bN  = tid >> 2;
    const int bCh = tid & 3;

    float c[2][4][4];
    #pragma unroll
    for (int mi = 0; mi < 2; mi++)
        #pragma unroll
        for (int ni = 0; ni < 4; ni++)
            #pragma unroll
            for (int r = 0; r < 4; r++) c[mi][ni][r] = 0.f;

    const int nkb = K / GBKH;

    float4 areg[4];
    {
        const float* ap = A + (size_t)(bm + aRow) * K + aPart * 16;
        #pragma unroll
        for (int i = 0; i < 4; i++) areg[i] = *(const float4*)(ap + 4 * i);
        cpasync16(&Bs[0][bN * BS_W + bCh * 4],
                  Wt + (size_t)(bn + bN) * K + bCh * 8);
        cpasync_commit();
    }

    for (int kb = 0; kb < nkb; kb++) {
        const int cur = kb & 1;
        {
            uint32_t w[8];
            #pragma unroll
            for (int i = 0; i < 4; i++) {
                w[2 * i]     = packh2(areg[i].x, areg[i].y);
                w[2 * i + 1] = packh2(areg[i].z, areg[i].w);
            }
            uint32_t* dst = &As[cur][aRow * AS_W + aPart * 8];
            *(uint4*)(dst)     = make_uint4(w[0], w[1], w[2], w[3]);
            *(uint4*)(dst + 4) = make_uint4(w[4], w[5], w[6], w[7]);
        }
        if (kb + 1 < nkb) {
            const int nxt = cur ^ 1;
            const int k0 = (kb + 1) * GBKH;
            const float* ap = A + (size_t)(bm + aRow) * K + k0 + aPart * 16;
            #pragma unroll
            for (int i = 0; i < 4; i++) areg[i] = *(const float4*)(ap + 4 * i);
            cpasync16(&Bs[nxt][bN * BS_W + bCh * 4],
                      Wt + (size_t)(bn + bN) * K + k0 + bCh * 8);
            cpasync_commit();
            cpasync_wait<1>();
        } else {
            cpasync_wait<0>();
        }
        __syncthreads();

        const uint32_t* as = As[cur];
        const uint32_t* bs = Bs[cur];
        #pragma unroll
        for (int kw = 0; kw < 16; kw += 8) {
            uint32_t af[2][4], bf[4][2];
            #pragma unroll
            for (int mi = 0; mi < 2; mi++) {
                const int m0 = warpM + mi * 16;
                af[mi][0] = as[(m0 + g    ) * AS_W + kw + tg    ];
                af[mi][1] = as[(m0 + g + 8) * AS_W + kw + tg    ];
                af[mi][2] = as[(m0 + g    ) * AS_W + kw + tg + 4];
                af[mi][3] = as[(m0 + g + 8) * AS_W + kw + tg + 4];
            }
            #pragma unroll
            for (int ni = 0; ni < 4; ni++) {
                const int n0 = warpN + ni * 8 + g;
                bf[ni][0] = bs[n0 * BS_W + kw + tg    ];
                bf[ni][1] = bs[n0 * BS_W + kw + tg + 4];
            }
            #pragma unroll
            for (int mi = 0; mi < 2; mi++)
                #pragma unroll
                for (int ni = 0; ni < 4; ni++)
                    mma_f16(c[mi][ni], af[mi], bf[ni]);
        }
        __syncthreads();
    }

    #pragma unroll
    for (int mi = 0; mi < 2; mi++) {
        #pragma unroll
        for (int ni = 0; ni < 4; ni++) {
            const int col = bn + warpN + ni * 8 + tg * 2;
            const float b0 = bias[col], b1 = bias[col + 1];
            #pragma unroll
            for (int h = 0; h < 2; h++) {
                const int row = bm + warpM + mi * 16 + g + h * 8;
                float v0 = c[mi][ni][2 * h + 0] + b0;
                float v1 = c[mi][ni][2 * h + 1] + b1;
                if (ep == EP_RES) {
                    const float2 rr = *(const float2*)(R + (size_t)row * N + col);
                    v0 += rr.x; v1 += rr.y;
                } else if (ep == EP_GELU) {
                    v0 = 0.5f * v0 * (1.0f + erff(v0 * 0.70710678118654752f));
                    v1 = 0.5f * v1 * (1.0f + erff(v1 * 0.70710678118654752f));
                }
                *(float2*)(C + (size_t)row * N + col) = make_float2(v0, v1);
            }
        }
    }
}

__global__ __launch_bounds__(256) void hgemm_ep(
    const float* __restrict__ A, const __half* __restrict__ Wt,
    const float* __restrict__ bias, const float* __restrict__ R,
    float* __restrict__ C, int M, int N, int K, int ep)
{
    hgemm_body(A, Wt, bias, R, C, M, N, K, ep,
               blockIdx.y * GBM, blockIdx.x * GBN);
}

__global__ __launch_bounds__(256) void hgemm_qkv(
    const float* __restrict__ Aq, const float* __restrict__ Akv,
    const __half* __restrict__ Wq, const float* __restrict__ bq,
    const __half* __restrict__ Wk, const float* __restrict__ bk,
    const __half* __restrict__ Wv, const float* __restrict__ bv,
    float* __restrict__ Cq, float* __restrict__ Ck, float* __restrict__ Cv)
{
    const int z = blockIdx.z;
    const float* A = (z == 0) ? Aq : Akv;
    const __half* W = (z == 0) ? Wq : (z == 1) ? Wk : Wv;
    const float* bia = (z == 0) ? bq : (z == 1) ? bk : bv;
    float* C = (z == 0) ? Cq : (z == 1) ? Ck : Cv;
    hgemm_body(A, W, bia, nullptr, C, ROWS, EMBED, EMBED, EP_BIAS,
               blockIdx.y * GBM, blockIdx.x * GBN);
}

// ================= fp16 tensor-core flash attention ==========================
// CTA: 64 queries x 1 head, 4 warps (16 q-rows each).
// S = Q K^T and O += P V via mma.m16n8k16 fp16, fp32 accum.
// P lives ONLY in registers: the S C-fragment ownership equals the PV
// A-fragment ownership for m16n8k16.
#define ATQ 64
#define ATK 64
#define KQ_W 36   // uint32 words per row (32 data + 4 pad): banks 4g+tg distinct
#define V_W  72   // Vs row stride in words: banks 8tg+g distinct

__global__ __launch_bounds__(128) void flash_f16(
    const float* __restrict__ Q, const float* __restrict__ Km,
    const float* __restrict__ V, float* __restrict__ O, int causal)
{
    __shared__ uint32_t Qs[ATQ * KQ_W];          // 9216 B
    __shared__ uint32_t Ks[ATK * KQ_W];          // 9216 B
    __shared__ uint32_t Vs[(ATK / 2) * V_W];     // 9216 B; [kp][dim] = {V[2kp][d],V[2kp+1][d]}

    const int b = blockIdx.z, h = blockIdx.y, qb = blockIdx.x;
    const int tid = threadIdx.x;
    const int wid = tid >> 5, lane = tid & 31;
    const int g = lane >> 2, tg = lane & 3;
    const int qbase = qb * ATQ;
    const int m0 = wid * 16;

    // ---- Q tile -> smem half (scaled by 1/sqrt(64)) ----
    #pragma unroll
    for (int i = 0; i < 8; i++) {
        const int idx = tid + i * 128;
        const int r = idx >> 4;
        const int w0 = (idx & 15) * 2;   // word index (2 words per float4)
        float4 qv = *(const float4*)(Q + ((size_t)(b * SEQ + qbase + r)) * EMBED + h * DH + w0 * 2);
        Qs[r * KQ_W + w0]     = packh2(qv.x * 0.125f, qv.y * 0.125f);
        Qs[r * KQ_W + w0 + 1] = packh2(qv.z * 0.125f, qv.w * 0.125f);
    }
    __syncthreads();

    // ---- Q fragments -> registers (4 k16 steps x 4 regs) ----
    uint32_t qf[4][4];
    #pragma unroll
    for (int s = 0; s < 4; s++) {
        qf[s][0] = Qs[(m0 + g    ) * KQ_W + 8 * s + tg    ];
        qf[s][1] = Qs[(m0 + g + 8) * KQ_W + 8 * s + tg    ];
        qf[s][2] = Qs[(m0 + g    ) * KQ_W + 8 * s + tg + 4];
        qf[s][3] = Qs[(m0 + g + 8) * KQ_W + 8 * s + tg + 4];
    }

    float oacc[8][4];
    #pragma unroll
    for (int ni = 0; ni < 8; ni++)
        #pragma unroll
        for (int r = 0; r < 4; r++) oacc[ni][r] = 0.f;
    float m0r = -1e30f, m1r = -1e30f, l0r = 0.f, l1r = 0.f;

    const int nkt = causal ? (qb + 1) : (SEQ / ATK);
    for (int kt = 0; kt < nkt; kt++) {
        // ---- K tile -> smem half, natural [key][dim] layout ----
        #pragma unroll
        for (int i = 0; i < 8; i++) {
            const int idx = tid + i * 128;
            const int r = idx >> 4;
            const int w0 = (idx & 15) * 2;
            float4 kk = *(const float4*)(Km + ((size_t)(b * SEQ + kt * ATK + r)) * EMBED + h * DH + w0 * 2);
            Ks[r * KQ_W + w0]     = packh2(kk.x, kk.y);
            Ks[r * KQ_W + w0 + 1] = packh2(kk.z, kk.w);
        }
        // ---- V tile -> smem, key-pair packed: Vs[kp][dim] ----
        #pragma unroll
        for (int i = 0; i < 4; i++) {
            const int idx = tid + i * 128;      // 0..511
            const int kp = idx >> 4;            // key pair 0..31
            const int c4 = (idx & 15) * 4;      // dim 0..60
            const size_t go = ((size_t)(b * SEQ + kt * ATK + 2 * kp)) * EMBED + h * DH + c4;
            float4 v0 = *(const float4*)(V + go);
            float4 v1 = *(const float4*)(V + go + EMBED);
            uint4 w;
            w.x = packh2(v0.x, v1.x);
            w.y = packh2(v0.y, v1.y);
            w.z = packh2(v0.z, v1.z);
            w.w = packh2(v0.w, v1.w);
            *(uint4*)(&Vs[kp * V_W + c4]) = w;
        }
        __syncthreads();

        // ---- S = Q K^T (fp16 MMA, fp32 accum) ----
        float sacc[8][4];
        #pragma unroll
        for (int ni = 0; ni < 8; ni++)
            #pragma unroll
            for (int r = 0; r < 4; r++) sacc[ni][r] = 0.f;
        #pragma unroll
        for (int s = 0; s < 4; s++) {
            #pragma unroll
            for (int ni = 0; ni < 8; ni++) {
                uint32_t bf[2];
                bf[0] = Ks[(ni * 8 + g) * KQ_W + 8 * s + tg    ];
                bf[1] = Ks[(ni * 8 + g) * KQ_W + 8 * s + tg + 4];
                mma_f16(sacc[ni], qf[s], bf);
            }
        }

        // ---- causal mask (diagonal tile only) ----
        if (causal && kt == qb) {
            const int r0 = qbase + m0 + g, r1 = r0 + 8;
            #pragma unroll
            for (int ni = 0; ni < 8; ni++) {
                const int c0 = kt * ATK + ni * 8 + 2 * tg;
                if (c0     > r0) sacc[ni][0] = -1e30f;
                if (c0 + 1 > r0) sacc[ni][1] = -1e30f;
                if (c0     > r1) sacc[ni][2] = -1e30f;
                if (c0 + 1 > r1) sacc[ni][3] = -1e30f;
            }
        }

        // ---- online softmax; P packed straight into A-fragments ----
        float mx0 = -1e30f, mx1 = -1e30f;
        #pragma unroll
        for (int ni = 0; ni < 8; ni++) {
            mx0 = fmaxf(mx0, fmaxf(sacc[ni][0], sacc[ni][1]));
            mx1 = fmaxf(mx1, fmaxf(sacc[ni][2], sacc[ni][3]));
        }
        mx0 = fmaxf(mx0, __shfl_xor_sync(0xffffffffu, mx0, 1));
        mx0 = fmaxf(mx0, __shfl_xor_sync(0xffffffffu, mx0, 2));
        mx1 = fmaxf(mx1, __shfl_xor_sync(0xffffffffu, mx1, 1));
        mx1 = fmaxf(mx1, __shfl_xor_sync(0xffffffffu, mx1, 2));
        const float mn0 = fmaxf(m0r, mx0);
        const float mn1 = fmaxf(m1r, mx1);
        const float cr0 = __expf(m0r - mn0);
        const float cr1 = __expf(m1r - mn1);
        m0r = mn0; m1r = mn1;

        uint32_t pf[8][2];
        float ls0 = 0.f, ls1 = 0.f;
        #pragma unroll
        for (int ni = 0; ni < 8; ni++) {
            const float p0 = __expf(sacc[ni][0] - mn0);
            const float p1 = __expf(sacc[ni][1] - mn0);
            const float p2 = __expf(sacc[ni][2] - mn1);
            const float p3 = __expf(sacc[ni][3] - mn1);
            ls0 += p0 + p1; ls1 += p2 + p3;
            pf[ni][0] = packh2(p0, p1);   // row g
            pf[ni][1] = packh2(p2, p3);   // row g+8
        }
        ls0 += __shfl_xor_sync(0xffffffffu, ls0, 1);
        ls0 += __shfl_xor_sync(0xffffffffu, ls0, 2);
        ls1 += __shfl_xor_sync(0xffffffffu, ls1, 1);
        ls1 += __shfl_xor_sync(0xffffffffu, ls1, 2);
        l0r = l0r * cr0 + ls0;
        l1r = l1r * cr1 + ls1;

        #pragma unroll
        for (int ni = 0; ni < 8; ni++) {
            oacc[ni][0] *= cr0; oacc[ni][1] *= cr0;
            oacc[ni][2] *= cr1; oacc[ni][3] *= cr1;
        }

        // ---- O += P V  (A = P from registers, B = packed Vs) ----
        #pragma unroll
        for (int s = 0; s < 4; s++) {
            uint32_t af[4];
            af[0] = pf[2 * s    ][0];   // row g,   keys 16s+2tg,+1
            af[1] = pf[2 * s    ][1];   // row g+8, same keys
            af[2] = pf[2 * s + 1][0];   // row g,   keys 16s+8+2tg,+1
            af[3] = pf[2 * s + 1][1];   // row g+8
            #pragma unroll
            for (int ni = 0; ni < 8; ni++) {
                uint32_t bf[2];
                bf[0] = Vs[(8 * s + tg    ) * V_W + ni * 8 + g];
                bf[1] = Vs[(8 * s + tg + 4) * V_W + ni * 8 + g];
                mma_f16(oacc[ni], af, bf);
            }
        }
        __syncthreads();   // before next tile overwrites Ks/Vs
    }

    const float inv0 = 1.f / l0r, inv1 = 1.f / l1r;
    #pragma unroll
    for (int ni = 0; ni < 8; ni++) {
        const size_t o0 = ((size_t)(b * SEQ + qbase + m0 + g)) * EMBED + h * DH + ni * 8 + 2 * tg;
        *(float2*)(O + o0)             = make_float2(oacc[ni][0] * inv0, oacc[ni][1] * inv0);
        *(float2*)(O + o0 + 8 * EMBED) = make_float2(oacc[ni][2] * inv1, oacc[ni][3] * inv1);
    }
}

// ---------------- LayerNorm over last dim (512) -----------------------------
__global__ __launch_bounds__(128) void layernorm_k(
    const float* __restrict__ X, const float* __restrict__ G,
    const float* __restrict__ Bt, float* __restrict__ Y)
{
    const int row = blockIdx.x;
    const int t = threadIdx.x;
    const float* xr = X + (size_t)row * EMBED;
    float4 v = *(const float4*)(xr + t * 4);
    float s  = v.x + v.y + v.z + v.w;
    float ss = v.x * v.x + v.y * v.y + v.z * v.z + v.w * v.w;
    #pragma unroll
    for (int o = 16; o > 0; o >>= 1) {
        s  += __shfl_xor_sync(0xffffffffu, s,  o);
        ss += __shfl_xor_sync(0xffffffffu, ss, o);
    }
    __shared__ float sh_s[4], sh_ss[4];
    const int w = t >> 5;
    if ((t & 31) == 0) { sh_s[w] = s; sh_ss[w] = ss; }
    __syncthreads();
    s  = sh_s[0] + sh_s[1] + sh_s[2] + sh_s[3];
    ss = sh_ss[0] + sh_ss[1] + sh_ss[2] + sh_ss[3];
    const float mean = s * (1.f / EMBED);
    const float var  = ss * (1.f / EMBED) - mean * mean;
    const float rstd = rsqrtf(var + 1e-5f);
    float4 gg = *(const float4*)(G  + t * 4);
    float4 bb = *(const float4*)(Bt + t * 4);
    float4 o;
    o.x = (v.x - mean) * rstd * gg.x + bb.x;
    o.y = (v.y - mean) * rstd * gg.y + bb.y;
    o.z = (v.z - mean) * rstd * gg.z + bb.z;
    o.w = (v.w - mean) * rstd * gg.w + bb.w;
    *(float4*)(Y + (size_t)row * EMBED + t * 4) = o;
}

// ---------------- launch --------------------------------------------------
extern "C" void kernel_launch(void* const* d_in, const int* in_sizes, int n_in,
                              void* d_out, int out_size)
{
    const float* x     = (const float*)d_in[0];
    const float* enc   = (const float*)d_in[1];
    const float* sa_wq = (const float*)d_in[2];
    const float* sa_bq = (const float*)d_in[3];
    const float* sa_wk = (const float*)d_in[4];
    const float* sa_bk = (const float*)d_in[5];
    const float* sa_wv = (const float*)d_in[6];
    const float* sa_bv = (const float*)d_in[7];
    const float* sa_wo = (const float*)d_in[8];
    const float* sa_bo = (const float*)d_in[9];
    const float* ca_wq = (const float*)d_in[10];
    const float* ca_bq = (const float*)d_in[11];
    const float* ca_wk = (const float*)d_in[12];
    const float* ca_bk = (const float*)d_in[13];
    const float* ca_wv = (const float*)d_in[14];
    const float* ca_bv = (const float*)d_in[15];
    const float* ca_wo = (const float*)d_in[16];
    const float* ca_bo = (const float*)d_in[17];
    const float* ln1_g = (const float*)d_in[18];
    const float* ln1_b = (const float*)d_in[19];
    const float* ln2_g = (const float*)d_in[20];
    const float* ln2_b = (const float*)d_in[21];
    const float* ln3_g = (const float*)d_in[22];
    const float* ln3_b = (const float*)d_in[23];
    const float* ff_w1 = (const float*)d_in[24];
    const float* ff_b1 = (const float*)d_in[25];
    const float* ff_w2 = (const float*)d_in[26];
    const float* ff_b2 = (const float*)d_in[27];
    float* out = (float*)d_out;

    float *q, *k, *v, *attn, *xb, *hb;
    __half* wh;
    cudaGetSymbolAddress((void**)&q,    g_q);
    cudaGetSymbolAddress((void**)&k,    g_k);
    cudaGetSymbolAddress((void**)&v,    g_v);
    cudaGetSymbolAddress((void**)&attn, g_attn);
    cudaGetSymbolAddress((void**)&xb,   g_x);
    cudaGetSymbolAddress((void**)&hb,   g_h);
    cudaGetSymbolAddress((void**)&wh,   g_wh);

    __half* w_saq = wh + 0 * WSQ;
    __half* w_sak = wh + 1 * WSQ;
    __half* w_sav = wh + 2 * WSQ;
    __half* w_sao = wh + 3 * WSQ;
    __half* w_caq = wh + 4 * WSQ;
    __half* w_cak = wh + 5 * WSQ;
    __half* w_cav = wh + 6 * WSQ;
    __half* w_cao = wh + 7 * WSQ;
    __half* w_ff1 = wh + 8 * WSQ;
    __half* w_ff2 = wh + 8 * WSQ + WFF;

    // ---- all weight transposes in one launch ----
    wconv_all<<<4096, 256>>>(sa_wq, sa_wk, sa_wv, sa_wo,
                             ca_wq, ca_wk, ca_wv, ca_wo,
                             ff_w1, ff_w2, wh);

    dim3 g512(EMBED / GBN, ROWS / GBM);      // (8, 32)
    dim3 gqkv(EMBED / GBN, ROWS / GBM, 3);   // (8, 32, 3)
    dim3 gff (FF    / GBN, ROWS / GBM);      // (32, 32)
    dim3 gfl (SEQ / ATQ, NH, BATCH);         // (32, 8, 2)

    // ---- self attention (causal) ----
    hgemm_qkv<<<gqkv, 256>>>(x, x, w_saq, sa_bq, w_sak, sa_bk, w_sav, sa_bv, q, k, v);
    flash_f16<<<gfl, 128>>>(q, k, v, attn, 1);
    hgemm_ep<<<g512, 256>>>(attn, w_sao, sa_bo, x, xb, ROWS, EMBED, EMBED, EP_RES);
    layernorm_k<<<ROWS, 128>>>(xb, ln1_g, ln1_b, xb);

    // ---- cross attention ----
    hgemm_qkv<<<gqkv, 256>>>(xb, enc, w_caq, ca_bq, w_cak, ca_bk, w_cav, ca_bv, q, k, v);
    flash_f16<<<gfl, 128>>>(q, k, v, attn, 0);
    hgemm_ep<<<g512, 256>>>(attn, w_cao, ca_bo, xb, xb, ROWS, EMBED, EMBED, EP_RES);
    layernorm_k<<<ROWS, 128>>>(xb, ln2_g, ln2_b, xb);

    // ---- feed-forward ----
    hgemm_ep<<<gff, 256>>>(xb, w_ff1, ff_b1, nullptr, hb, ROWS, FF, EMBED, EP_GELU);
    hgemm_ep<<<g512, 256>>>(hb, w_ff2, ff_b2, xb, xb, ROWS, EMBED, FF, EP_RES);
    layernorm_k<<<ROWS, 128>>>(xb, ln3_g, ln3_b, out);
}

// round 11
// speedup vs baseline: 9.4673x; 1.0789x over previous
#include <cuda_runtime.h>
#include <cuda_fp16.h>
#include <math.h>
#include <stdint.h>

#define EMBED 512
#define NH    8
#define DH    64
#define BATCH 2
#define SEQ   2048
#define ROWS  (BATCH*SEQ)   // 4096
#define FF    2048

// ---------------- scratch (no allocation allowed) ----------------
__device__ float g_q[ROWS*EMBED];
__device__ float g_k[ROWS*EMBED];
__device__ float g_v[ROWS*EMBED];
__device__ float g_attn[ROWS*EMBED];
__device__ float g_x[ROWS*EMBED];
__device__ float g_h[ROWS*FF];
#define WSQ (512*512)
#define WFF (512*2048)
__device__ __half g_wh[8*WSQ + 2*WFF];

#define EP_BIAS 0
#define EP_RES  1
#define EP_GELU 2

__device__ __forceinline__ void mma_f16(
    float c[4], const uint32_t a[4], const uint32_t b[2])
{
    asm volatile(
        "mma.sync.aligned.m16n8k16.row.col.f32.f16.f16.f32 "
        "{%0,%1,%2,%3}, {%4,%5,%6,%7}, {%8,%9}, {%0,%1,%2,%3};"
        : "+f"(c[0]), "+f"(c[1]), "+f"(c[2]), "+f"(c[3])
        : "r"(a[0]), "r"(a[1]), "r"(a[2]), "r"(a[3]), "r"(b[0]), "r"(b[1]));
}

__device__ __forceinline__ void ldsm_x4(uint32_t r[4], const void* sptr) {
    uint32_t a = (uint32_t)__cvta_generic_to_shared(sptr);
    asm volatile("ldmatrix.sync.aligned.m8n8.x4.shared.b16 {%0,%1,%2,%3}, [%4];"
        : "=r"(r[0]), "=r"(r[1]), "=r"(r[2]), "=r"(r[3]) : "r"(a));
}

__device__ __forceinline__ void cpasync16(void* sptr, const void* gptr) {
    uint32_t s = (uint32_t)__cvta_generic_to_shared(sptr);
    asm volatile("cp.async.ca.shared.global [%0], [%1], 16;\n" :: "r"(s), "l"(gptr));
}
__device__ __forceinline__ void cpasync_commit() {
    asm volatile("cp.async.commit_group;\n" ::: "memory");
}
template <int N>
__device__ __forceinline__ void cpasync_wait() {
    asm volatile("cp.async.wait_group %0;\n" :: "n"(N) : "memory");
}

__device__ __forceinline__ uint32_t packh2(float a, float b) {
    half2 h = __floats2half2_rn(a, b);
    return *(uint32_t*)&h;
}

// ---------------- ALL weight transposes in ONE launch -----------------------
__global__ __launch_bounds__(256) void wconv_all(
    const float* s0, const float* s1, const float* s2, const float* s3,
    const float* s4, const float* s5, const float* s6, const float* s7,
    const float* s8, const float* s9, __half* __restrict__ wh)
{
    __shared__ float tile[32][33];
    const int id = blockIdx.x;
    const float* W; __half* Wt; int K, N, bx, by;
    if (id < 2048) {
        const float* tab[8] = {s0, s1, s2, s3, s4, s5, s6, s7};
        const int wi = id >> 8, rem = id & 255;
        W = tab[wi]; Wt = wh + (size_t)wi * WSQ;
        K = 512; N = 512; bx = rem & 15; by = rem >> 4;
    } else if (id < 3072) {
        const int rem = id - 2048;
        W = s8; Wt = wh + (size_t)8 * WSQ;
        K = 512; N = 2048; bx = rem & 63; by = rem >> 6;
    } else {
        const int rem = id - 3072;
        W = s9; Wt = wh + (size_t)8 * WSQ + WFF;
        K = 2048; N = 512; bx = rem & 15; by = rem >> 4;
    }
    const int n0 = bx * 32, k0 = by * 32;
    const int tx = threadIdx.x & 31, ty = threadIdx.x >> 5;
    #pragma unroll
    for (int j = 0; j < 4; j++)
        tile[ty + j * 8][tx] = W[(size_t)(k0 + ty + j * 8) * N + n0 + tx];
    __syncthreads();
    #pragma unroll
    for (int j = 0; j < 4; j++)
        Wt[(size_t)(n0 + ty + j * 8) * K + k0 + tx] =
            __float2half_rn(tile[tx][ty + j * 8]);
}

// ================= fp16 tensor-core GEMM, ldmatrix + templated tile =========
// BM=128: 8 warps 4x2, warp 32x32.  BM=64: 8 warps 2x4, warp 32x16 (2x grid).
#define GBN 64
#define GBKH 32
#define AS_W 20
#define BS_W 20

template<int BM>
__device__ __forceinline__ void hgemm_body(
    const float* __restrict__ A, const __half* __restrict__ Wt,
    const float* __restrict__ bias, const float* __restrict__ R,
    float* __restrict__ C, int M, int N, int K, int ep,
    int bm, int bn)
{
    constexpr int WCOLS = (BM == 128) ? 2 : 4;
    constexpr int MI = 2;
    constexpr int NI = (BM == 128) ? 4 : 2;
    constexpr int FPT = BM / 8;         // A floats per thread (16 or 8)
    constexpr int F4  = FPT / 4;        // float4 loads per thread (4 or 2)
    constexpr int TPR = 32 / FPT;       // threads per A row (2 or 4)

    __shared__ uint32_t As[2][BM * AS_W];
    __shared__ uint32_t Bs[2][GBN * BS_W];

    const int tid  = threadIdx.x;
    const int wid  = tid >> 5;
    const int lane = tid & 31;
    const int g    = lane >> 2;
    const int tg   = lane & 3;
    const int warpM = (wid / WCOLS) * 32;
    const int warpN = (wid % WCOLS) * (GBN / WCOLS);

    const int aRow  = tid / TPR;
    const int aPart = tid % TPR;
    const int bN  = tid >> 2;
    const int bCh = tid & 3;

    // ldmatrix per-lane address components
    const int aLRow = lane & 15;
    const int aLW   = (lane & 16) ? 4 : 0;
    const int bLRow = ((lane & 16) ? 8 : 0) + (lane & 7);
    const int bLW   = (lane & 8) ? 4 : 0;

    float c[MI][NI][4];
    #pragma unroll
    for (int mi = 0; mi < MI; mi++)
        #pragma unroll
        for (int ni = 0; ni < NI; ni++)
            #pragma unroll
            for (int r = 0; r < 4; r++) c[mi][ni][r] = 0.f;

    const int nkb = K / GBKH;

    float4 areg[F4];
    {
        const float* ap = A + (size_t)(bm + aRow) * K + aPart * FPT;
        #pragma unroll
        for (int i = 0; i < F4; i++) areg[i] = *(const float4*)(ap + 4 * i);
        cpasync16(&Bs[0][bN * BS_W + bCh * 4],
                  Wt + (size_t)(bn + bN) * K + bCh * 8);
        cpasync_commit();
    }

    for (int kb = 0; kb < nkb; kb++) {
        const int cur = kb & 1;
        {
            uint32_t w[F4 * 2];
            #pragma unroll
            for (int i = 0; i < F4; i++) {
                w[2 * i]     = packh2(areg[i].x, areg[i].y);
                w[2 * i + 1] = packh2(areg[i].z, areg[i].w);
            }
            uint32_t* dst = &As[cur][aRow * AS_W + aPart * (FPT / 2)];
            #pragma unroll
            for (int j = 0; j < F4 / 2; j++)
                *(uint4*)(dst + 4 * j) =
                    make_uint4(w[4 * j], w[4 * j + 1], w[4 * j + 2], w[4 * j + 3]);
        }
        if (kb + 1 < nkb) {
            const int nxt = cur ^ 1;
            const int k0 = (kb + 1) * GBKH;
            const float* ap = A + (size_t)(bm + aRow) * K + k0 + aPart * FPT;
            #pragma unroll
            for (int i = 0; i < F4; i++) areg[i] = *(const float4*)(ap + 4 * i);
            cpasync16(&Bs[nxt][bN * BS_W + bCh * 4],
                      Wt + (size_t)(bn + bN) * K + k0 + bCh * 8);
            cpasync_commit();
            cpasync_wait<1>();
        } else {
            cpasync_wait<0>();
        }
        __syncthreads();

        const uint32_t* as = As[cur];
        const uint32_t* bs = Bs[cur];
        #pragma unroll
        for (int kw = 0; kw < 16; kw += 8) {
            uint32_t af[MI][4], bf[NI][2];
            #pragma unroll
            for (int mi = 0; mi < MI; mi++)
                ldsm_x4(af[mi], &as[(warpM + mi * 16 + aLRow) * AS_W + kw + aLW]);
            #pragma unroll
            for (int np = 0; np < NI / 2; np++)
                ldsm_x4(&bf[np * 2][0],
                        &bs[(warpN + np * 16 + bLRow) * BS_W + kw + bLW]);
            #pragma unroll
            for (int mi = 0; mi < MI; mi++)
                #pragma unroll
                for (int ni = 0; ni < NI; ni++)
                    mma_f16(c[mi][ni], af[mi], bf[ni]);
        }
        __syncthreads();
    }

    #pragma unroll
    for (int mi = 0; mi < MI; mi++) {
        #pragma unroll
        for (int ni = 0; ni < NI; ni++) {
            const int col = bn + warpN + ni * 8 + tg * 2;
            const float b0 = bias[col], b1 = bias[col + 1];
            #pragma unroll
            for (int h = 0; h < 2; h++) {
                const int row = bm + warpM + mi * 16 + g + h * 8;
                float v0 = c[mi][ni][2 * h + 0] + b0;
                float v1 = c[mi][ni][2 * h + 1] + b1;
                if (ep == EP_RES) {
                    const float2 rr = *(const float2*)(R + (size_t)row * N + col);
                    v0 += rr.x; v1 += rr.y;
                } else if (ep == EP_GELU) {
                    v0 = 0.5f * v0 * (1.0f + erff(v0 * 0.70710678118654752f));
                    v1 = 0.5f * v1 * (1.0f + erff(v1 * 0.70710678118654752f));
                }
                *(float2*)(C + (size_t)row * N + col) = make_float2(v0, v1);
            }
        }
    }
}

__global__ __launch_bounds__(256) void hgemm_ep128(
    const float* __restrict__ A, const __half* __restrict__ Wt,
    const float* __restrict__ bias, const float* __restrict__ R,
    float* __restrict__ C, int M, int N, int K, int ep)
{
    hgemm_body<128>(A, Wt, bias, R, C, M, N, K, ep,
                    blockIdx.y * 128, blockIdx.x * GBN);
}

__global__ __launch_bounds__(256) void hgemm_ep64(
    const float* __restrict__ A, const __half* __restrict__ Wt,
    const float* __restrict__ bias, const float* __restrict__ R,
    float* __restrict__ C, int M, int N, int K, int ep)
{
    hgemm_body<64>(A, Wt, bias, R, C, M, N, K, ep,
                   blockIdx.y * 64, blockIdx.x * GBN);
}

__global__ __launch_bounds__(256) void hgemm_qkv(
    const float* __restrict__ Aq, const float* __restrict__ Akv,
    const __half* __restrict__ Wq, const float* __restrict__ bq,
    const __half* __restrict__ Wk, const float* __restrict__ bk,
    const __half* __restrict__ Wv, const float* __restrict__ bv,
    float* __restrict__ Cq, float* __restrict__ Ck, float* __restrict__ Cv)
{
    const int z = blockIdx.z;
    const float* A = (z == 0) ? Aq : Akv;
    const __half* W = (z == 0) ? Wq : (z == 1) ? Wk : Wv;
    const float* bia = (z == 0) ? bq : (z == 1) ? bk : bv;
    float* C = (z == 0) ? Cq : (z == 1) ? Ck : Cv;
    hgemm_body<128>(A, W, bia, nullptr, C, ROWS, EMBED, EMBED, EP_BIAS,
                    blockIdx.y * 128, blockIdx.x * GBN);
}

// ================= fp16 tensor-core flash attention (R9 + K via ldmatrix) ===
#define ATQ 64
#define ATK 64
#define KQ_W 36
#define V_W  72

__global__ __launch_bounds__(128) void flash_f16(
    const float* __restrict__ Q, const float* __restrict__ Km,
    const float* __restrict__ V, float* __restrict__ O, int causal)
{
    __shared__ uint32_t Qs[ATQ * KQ_W];
    __shared__ uint32_t Ks[ATK * KQ_W];
    __shared__ uint32_t Vs[(ATK / 2) * V_W];

    const int b = blockIdx.z, h = blockIdx.y, qb = blockIdx.x;
    const int tid = threadIdx.x;
    const int wid = tid >> 5, lane = tid & 31;
    const int g = lane >> 2, tg = lane & 3;
    const int qbase = qb * ATQ;
    const int m0 = wid * 16;

    const int kLRow = ((lane & 16) ? 8 : 0) + (lane & 7);
    const int kLW   = (lane & 8) ? 4 : 0;

    #pragma unroll
    for (int i = 0; i < 8; i++) {
        const int idx = tid + i * 128;
        const int r = idx >> 4;
        const int w0 = (idx & 15) * 2;
        float4 qv = *(const float4*)(Q + ((size_t)(b * SEQ + qbase + r)) * EMBED + h * DH + w0 * 2);
        Qs[r * KQ_W + w0]     = packh2(qv.x * 0.125f, qv.y * 0.125f);
        Qs[r * KQ_W + w0 + 1] = packh2(qv.z * 0.125f, qv.w * 0.125f);
    }
    __syncthreads();

    uint32_t qf[4][4];
    #pragma unroll
    for (int s = 0; s < 4; s++) {
        qf[s][0] = Qs[(m0 + g    ) * KQ_W + 8 * s + tg    ];
        qf[s][1] = Qs[(m0 + g + 8) * KQ_W + 8 * s + tg    ];
        qf[s][2] = Qs[(m0 + g    ) * KQ_W + 8 * s + tg + 4];
        qf[s][3] = Qs[(m0 + g + 8) * KQ_W + 8 * s + tg + 4];
    }

    float oacc[8][4];
    #pragma unroll
    for (int ni = 0; ni < 8; ni++)
        #pragma unroll
        for (int r = 0; r < 4; r++) oacc[ni][r] = 0.f;
    float m0r = -1e30f, m1r = -1e30f, l0r = 0.f, l1r = 0.f;

    const int nkt = causal ? (qb + 1) : (SEQ / ATK);
    for (int kt = 0; kt < nkt; kt++) {
        #pragma unroll
        for (int i = 0; i < 8; i++) {
            const int idx = tid + i * 128;
            const int r = idx >> 4;
            const int w0 = (idx & 15) * 2;
            float4 kk = *(const float4*)(Km + ((size_t)(b * SEQ + kt * ATK + r)) * EMBED + h * DH + w0 * 2);
            Ks[r * KQ_W + w0]     = packh2(kk.x, kk.y);
            Ks[r * KQ_W + w0 + 1] = packh2(kk.z, kk.w);
        }
        #pragma unroll
        for (int i = 0; i < 4; i++) {
            const int idx = tid + i * 128;
            const int kp = idx >> 4;
            const int c4 = (idx & 15) * 4;
            const size_t go = ((size_t)(b * SEQ + kt * ATK + 2 * kp)) * EMBED + h * DH + c4;
            float4 v0 = *(const float4*)(V + go);
            float4 v1 = *(const float4*)(V + go + EMBED);
            uint4 w;
            w.x = packh2(v0.x, v1.x);
            w.y = packh2(v0.y, v1.y);
            w.z = packh2(v0.z, v1.z);
            w.w = packh2(v0.w, v1.w);
            *(uint4*)(&Vs[kp * V_W + c4]) = w;
        }
        __syncthreads();

        // ---- S = Q K^T  (K fragments via ldmatrix.x4) ----
        float sacc[8][4];
        #pragma unroll
        for (int ni = 0; ni < 8; ni++)
            #pragma unroll
            for (int r = 0; r < 4; r++) sacc[ni][r] = 0.f;
        #pragma unroll
        for (int s = 0; s < 4; s++) {
            uint32_t kf[8][2];
            #pragma unroll
            for (int np = 0; np < 4; np++)
                ldsm_x4(&kf[np * 2][0],
                        &Ks[(np * 16 + kLRow) * KQ_W + 8 * s + kLW]);
            #pragma unroll
            for (int ni = 0; ni < 8; ni++)
                mma_f16(sacc[ni], qf[s], kf[ni]);
        }

        if (causal && kt == qb) {
            const int r0 = qbase + m0 + g, r1 = r0 + 8;
            #pragma unroll
            for (int ni = 0; ni < 8; ni++) {
                const int c0 = kt * ATK + ni * 8 + 2 * tg;
                if (c0     > r0) sacc[ni][0] = -1e30f;
                if (c0 + 1 > r0) sacc[ni][1] = -1e30f;
                if (c0     > r1) sacc[ni][2] = -1e30f;
                if (c0 + 1 > r1) sacc[ni][3] = -1e30f;
            }
        }

        float mx0 = -1e30f, mx1 = -1e30f;
        #pragma unroll
        for (int ni = 0; ni < 8; ni++) {
            mx0 = fmaxf(mx0, fmaxf(sacc[ni][0], sacc[ni][1]));
            mx1 = fmaxf(mx1, fmaxf(sacc[ni][2], sacc[ni][3]));
        }
        mx0 = fmaxf(mx0, __shfl_xor_sync(0xffffffffu, mx0, 1));
        mx0 = fmaxf(mx0, __shfl_xor_sync(0xffffffffu, mx0, 2));
        mx1 = fmaxf(mx1, __shfl_xor_sync(0xffffffffu, mx1, 1));
        mx1 = fmaxf(mx1, __shfl_xor_sync(0xffffffffu, mx1, 2));
        const float mn0 = fmaxf(m0r, mx0);
        const float mn1 = fmaxf(m1r, mx1);
        const float cr0 = __expf(m0r - mn0);
        const float cr1 = __expf(m1r - mn1);
        m0r = mn0; m1r = mn1;

        uint32_t pf[8][2];
        float ls0 = 0.f, ls1 = 0.f;
        #pragma unroll
        for (int ni = 0; ni < 8; ni++) {
            const float p0 = __expf(sacc[ni][0] - mn0);
            const float p1 = __expf(sacc[ni][1] - mn0);
            const float p2 = __expf(sacc[ni][2] - mn1);
            const float p3 = __expf(sacc[ni][3] - mn1);
            ls0 += p0 + p1; ls1 += p2 + p3;
            pf[ni][0] = packh2(p0, p1);
            pf[ni][1] = packh2(p2, p3);
        }
        ls0 += __shfl_xor_sync(0xffffffffu, ls0, 1);
        ls0 += __shfl_xor_sync(0xffffffffu, ls0, 2);
        ls1 += __shfl_xor_sync(0xffffffffu, ls1, 1);
        ls1 += __shfl_xor_sync(0xffffffffu, ls1, 2);
        l0r = l0r * cr0 + ls0;
        l1r = l1r * cr1 + ls1;

        #pragma unroll
        for (int ni = 0; ni < 8; ni++) {
            oacc[ni][0] *= cr0; oacc[ni][1] *= cr0;
            oacc[ni][2] *= cr1; oacc[ni][3] *= cr1;
        }

        #pragma unroll
        for (int s = 0; s < 4; s++) {
            uint32_t af[4];
            af[0] = pf[2 * s    ][0];
            af[1] = pf[2 * s    ][1];
            af[2] = pf[2 * s + 1][0];
            af[3] = pf[2 * s + 1][1];
            #pragma unroll
            for (int ni = 0; ni < 8; ni++) {
                uint32_t bf[2];
                bf[0] = Vs[(8 * s + tg    ) * V_W + ni * 8 + g];
                bf[1] = Vs[(8 * s + tg + 4) * V_W + ni * 8 + g];
                mma_f16(oacc[ni], af, bf);
            }
        }
        __syncthreads();
    }

    const float inv0 = 1.f / l0r, inv1 = 1.f / l1r;
    #pragma unroll
    for (int ni = 0; ni < 8; ni++) {
        const size_t o0 = ((size_t)(b * SEQ + qbase + m0 + g)) * EMBED + h * DH + ni * 8 + 2 * tg;
        *(float2*)(O + o0)             = make_float2(oacc[ni][0] * inv0, oacc[ni][1] * inv0);
        *(float2*)(O + o0 + 8 * EMBED) = make_float2(oacc[ni][2] * inv1, oacc[ni][3] * inv1);
    }
}

// ---------------- LayerNorm over last dim (512) -----------------------------
__global__ __launch_bounds__(128) void layernorm_k(
    const float* __restrict__ X, const float* __restrict__ G,
    const float* __restrict__ Bt, float* __restrict__ Y)
{
    const int row = blockIdx.x;
    const int t = threadIdx.x;
    const float* xr = X + (size_t)row * EMBED;
    float4 v = *(const float4*)(xr + t * 4);
    float s  = v.x + v.y + v.z + v.w;
    float ss = v.x * v.x + v.y * v.y + v.z * v.z + v.w * v.w;
    #pragma unroll
    for (int o = 16; o > 0; o >>= 1) {
        s  += __shfl_xor_sync(0xffffffffu, s,  o);
        ss += __shfl_xor_sync(0xffffffffu, ss, o);
    }
    __shared__ float sh_s[4], sh_ss[4];
    const int w = t >> 5;
    if ((t & 31) == 0) { sh_s[w] = s; sh_ss[w] = ss; }
    __syncthreads();
    s  = sh_s[0] + sh_s[1] + sh_s[2] + sh_s[3];
    ss = sh_ss[0] + sh_ss[1] + sh_ss[2] + sh_ss[3];
    const float mean = s * (1.f / EMBED);
    const float var  = ss * (1.f / EMBED) - mean * mean;
    const float rstd = rsqrtf(var + 1e-5f);
    float4 gg = *(const float4*)(G  + t * 4);
    float4 bb = *(const float4*)(Bt + t * 4);
    float4 o;
    o.x = (v.x - mean) * rstd * gg.x + bb.x;
    o.y = (v.y - mean) * rstd * gg.y + bb.y;
    o.z = (v.z - mean) * rstd * gg.z + bb.z;
    o.w = (v.w - mean) * rstd * gg.w + bb.w;
    *(float4*)(Y + (size_t)row * EMBED + t * 4) = o;
}

// ---------------- launch --------------------------------------------------
extern "C" void kernel_launch(void* const* d_in, const int* in_sizes, int n_in,
                              void* d_out, int out_size)
{
    const float* x     = (const float*)d_in[0];
    const float* enc   = (const float*)d_in[1];
    const float* sa_wq = (const float*)d_in[2];
    const float* sa_bq = (const float*)d_in[3];
    const float* sa_wk = (const float*)d_in[4];
    const float* sa_bk = (const float*)d_in[5];
    const float* sa_wv = (const float*)d_in[6];
    const float* sa_bv = (const float*)d_in[7];
    const float* sa_wo = (const float*)d_in[8];
    const float* sa_bo = (const float*)d_in[9];
    const float* ca_wq = (const float*)d_in[10];
    const float* ca_bq = (const float*)d_in[11];
    const float* ca_wk = (const float*)d_in[12];
    const float* ca_bk = (const float*)d_in[13];
    const float* ca_wv = (const float*)d_in[14];
    const float* ca_bv = (const float*)d_in[15];
    const float* ca_wo = (const float*)d_in[16];
    const float* ca_bo = (const float*)d_in[17];
    const float* ln1_g = (const float*)d_in[18];
    const float* ln1_b = (const float*)d_in[19];
    const float* ln2_g = (const float*)d_in[20];
    const float* ln2_b = (const float*)d_in[21];
    const float* ln3_g = (const float*)d_in[22];
    const float* ln3_b = (const float*)d_in[23];
    const float* ff_w1 = (const float*)d_in[24];
    const float* ff_b1 = (const float*)d_in[25];
    const float* ff_w2 = (const float*)d_in[26];
    const float* ff_b2 = (const float*)d_in[27];
    float* out = (float*)d_out;

    float *q, *k, *v, *attn, *xb, *hb;
    __half* wh;
    cudaGetSymbolAddress((void**)&q,    g_q);
    cudaGetSymbolAddress((void**)&k,    g_k);
    cudaGetSymbolAddress((void**)&v,    g_v);
    cudaGetSymbolAddress((void**)&attn, g_attn);
    cudaGetSymbolAddress((void**)&xb,   g_x);
    cudaGetSymbolAddress((void**)&hb,   g_h);
    cudaGetSymbolAddress((void**)&wh,   g_wh);

    __half* w_saq = wh + 0 * WSQ;
    __half* w_sak = wh + 1 * WSQ;
    __half* w_sav = wh + 2 * WSQ;
    __half* w_sao = wh + 3 * WSQ;
    __half* w_caq = wh + 4 * WSQ;
    __half* w_cak = wh + 5 * WSQ;
    __half* w_cav = wh + 6 * WSQ;
    __half* w_cao = wh + 7 * WSQ;
    __half* w_ff1 = wh + 8 * WSQ;
    __half* w_ff2 = wh + 8 * WSQ + WFF;

    wconv_all<<<4096, 256>>>(sa_wq, sa_wk, sa_wv, sa_wo,
                             ca_wq, ca_wk, ca_wv, ca_wo,
                             ff_w1, ff_w2, wh);

    dim3 g64 (EMBED / GBN, ROWS / 64);       // (8, 64) for N=512 GEMMs
    dim3 gqkv(EMBED / GBN, ROWS / 128, 3);   // (8, 32, 3)
    dim3 gff (FF    / GBN, ROWS / 128);      // (32, 32)
    dim3 gfl (SEQ / ATQ, NH, BATCH);         // (32, 8, 2)

    // ---- self attention (causal) ----
    hgemm_qkv<<<gqkv, 256>>>(x, x, w_saq, sa_bq, w_sak, sa_bk, w_sav, sa_bv, q, k, v);
    flash_f16<<<gfl, 128>>>(q, k, v, attn, 1);
    hgemm_ep64<<<g64, 256>>>(attn, w_sao, sa_bo, x, xb, ROWS, EMBED, EMBED, EP_RES);
    layernorm_k<<<ROWS, 128>>>(xb, ln1_g, ln1_b, xb);

    // ---- cross attention ----
    hgemm_qkv<<<gqkv, 256>>>(xb, enc, w_caq, ca_bq, w_cak, ca_bk, w_cav, ca_bv, q, k, v);
    flash_f16<<<gfl, 128>>>(q, k, v, attn, 0);
    hgemm_ep64<<<g64, 256>>>(attn, w_cao, ca_bo, xb, xb, ROWS, EMBED, EMBED, EP_RES);
    layernorm_k<<<ROWS, 128>>>(xb, ln2_g, ln2_b, xb);

    // ---- feed-forward ----
    hgemm_ep128<<<gff, 256>>>(xb, w_ff1, ff_b1, nullptr, hb, ROWS, FF, EMBED, EP_GELU);
    hgemm_ep64<<<g64, 256>>>(hb, w_ff2, ff_b2, xb, xb, ROWS, EMBED, FF, EP_RES);
    layernorm_k<<<ROWS, 128>>>(xb, ln3_g, ln3_b, out);
}

// round 17
// speedup vs baseline: 12.1204x; 1.2802x over previous
#include <cuda_runtime.h>
#include <cuda_fp16.h>
#include <math.h>
#include <stdint.h>

#define EMBED 512
#define NH    8
#define DH    64
#define BATCH 2
#define SEQ   2048
#define ROWS  (BATCH*SEQ)   // 4096
#define FF    2048

// ---------------- scratch (no allocation allowed) ----------------
__device__ float  g_x[ROWS*EMBED];        // fp32 residual chain
__device__ __half g_xh[ROWS*EMBED];       // fp16 x
__device__ __half g_ench[ROWS*EMBED];     // fp16 encoder_output
__device__ __half g_qh[ROWS*EMBED];
__device__ __half g_kh[ROWS*EMBED];
__device__ __half g_vh[ROWS*EMBED];
__device__ __half g_attnh[ROWS*EMBED];
__device__ __half g_xbh[ROWS*EMBED];      // fp16 mirror of LN output
__device__ __half g_hh[ROWS*FF];
#define WSQ (512*512)
#define WFF (512*2048)
__device__ __half g_wh[8*WSQ + 2*WFF];

#define EP_BIAS 0   // -> fp16 C
#define EP_RES  1   // -> fp32 C (+residual)
#define EP_GELU 2   // -> fp16 C

__device__ __forceinline__ void mma_f16(
    float c[4], const uint32_t a[4], const uint32_t b[2])
{
    asm volatile(
        "mma.sync.aligned.m16n8k16.row.col.f32.f16.f16.f32 "
        "{%0,%1,%2,%3}, {%4,%5,%6,%7}, {%8,%9}, {%0,%1,%2,%3};"
        : "+f"(c[0]), "+f"(c[1]), "+f"(c[2]), "+f"(c[3])
        : "r"(a[0]), "r"(a[1]), "r"(a[2]), "r"(a[3]), "r"(b[0]), "r"(b[1]));
}

__device__ __forceinline__ void ldsm_x4(uint32_t r[4], const void* sptr) {
    uint32_t a = (uint32_t)__cvta_generic_to_shared(sptr);
    asm volatile("ldmatrix.sync.aligned.m8n8.x4.shared.b16 {%0,%1,%2,%3}, [%4];"
        : "=r"(r[0]), "=r"(r[1]), "=r"(r[2]), "=r"(r[3]) : "r"(a));
}

__device__ __forceinline__ void cpasync16(void* sptr, const void* gptr) {
    uint32_t s = (uint32_t)__cvta_generic_to_shared(sptr);
    asm volatile("cp.async.ca.shared.global [%0], [%1], 16;\n" :: "r"(s), "l"(gptr));
}
__device__ __forceinline__ void cpasync_commit() {
    asm volatile("cp.async.commit_group;\n" ::: "memory");
}
template <int N>
__device__ __forceinline__ void cpasync_wait() {
    asm volatile("cp.async.wait_group %0;\n" :: "n"(N) : "memory");
}

__device__ __forceinline__ uint32_t packh2(float a, float b) {
    half2 h = __floats2half2_rn(a, b);
    return *(uint32_t*)&h;
}

__device__ __forceinline__ uint32_t hmul2_u(uint32_t w, half2 s) {
    half2 h = __hmul2(*(half2*)&w, s);
    return *(uint32_t*)&h;
}

// ---------------- x/enc fp32 -> fp16, one launch ----------------------------
__global__ __launch_bounds__(256) void xconv(
    const float* __restrict__ x, const float* __restrict__ enc,
    __half* __restrict__ xh, __half* __restrict__ ench)
{
    const float* src = blockIdx.y ? enc : x;
    __half* dst = blockIdx.y ? ench : xh;
    const int i = blockIdx.x * 256 + threadIdx.x;        // float4 index
    float4 v = ((const float4*)src)[i];
    uint2 o = make_uint2(packh2(v.x, v.y), packh2(v.z, v.w));
    ((uint2*)dst)[i] = o;
}

// ---------------- ALL weight transposes in ONE launch -----------------------
__global__ __launch_bounds__(256) void wconv_all(
    const float* s0, const float* s1, const float* s2, const float* s3,
    const float* s4, const float* s5, const float* s6, const float* s7,
    const float* s8, const float* s9, __half* __restrict__ wh)
{
    __shared__ float tile[32][33];
    const int id = blockIdx.x;
    const float* W; __half* Wt; int K, N, bx, by;
    if (id < 2048) {
        const float* tab[8] = {s0, s1, s2, s3, s4, s5, s6, s7};
        const int wi = id >> 8, rem = id & 255;
        W = tab[wi]; Wt = wh + (size_t)wi * WSQ;
        K = 512; N = 512; bx = rem & 15; by = rem >> 4;
    } else if (id < 3072) {
        const int rem = id - 2048;
        W = s8; Wt = wh + (size_t)8 * WSQ;
        K = 512; N = 2048; bx = rem & 63; by = rem >> 6;
    } else {
        const int rem = id - 3072;
        W = s9; Wt = wh + (size_t)8 * WSQ + WFF;
        K = 2048; N = 512; bx = rem & 15; by = rem >> 4;
    }
    const int n0 = bx * 32, k0 = by * 32;
    const int tx = threadIdx.x & 31, ty = threadIdx.x >> 5;
    #pragma unroll
    for (int j = 0; j < 4; j++)
        tile[ty + j * 8][tx] = W[(size_t)(k0 + ty + j * 8) * N + n0 + tx];
    __syncthreads();
    #pragma unroll
    for (int j = 0; j < 4; j++)
        Wt[(size_t)(n0 + ty + j * 8) * K + k0 + tx] =
            __float2half_rn(tile[tx][ty + j * 8]);
}

// ================= fp16 GEMM: cp.async A+B, ldmatrix, fp16/fp32 epilogues ===
#define GBN 64
#define GBKH 32
#define AS_W 20
#define BS_W 20

template<int BM>
__device__ __forceinline__ void hgemm_body(
    const __half* __restrict__ A, const __half* __restrict__ Wt,
    const float* __restrict__ bias, const float* __restrict__ R,
    float* __restrict__ Cf, __half* __restrict__ Ch,
    int M, int N, int K, int ep, int bm, int bn)
{
    constexpr int WCOLS = (BM == 128) ? 2 : 4;
    constexpr int MI = 2;
    constexpr int NI = (BM == 128) ? 4 : 2;
    constexpr int AIT = BM / 64;        // A cp.async chunks per thread (2 or 1)

    __shared__ uint32_t As[2][BM * AS_W];
    __shared__ uint32_t Bs[2][GBN * BS_W];

    const int tid  = threadIdx.x;
    const int wid  = tid >> 5;
    const int lane = tid & 31;
    const int g    = lane >> 2;
    const int tg   = lane & 3;
    const int warpM = (wid / WCOLS) * 32;
    const int warpN = (wid % WCOLS) * (GBN / WCOLS);

    const int bN  = tid >> 2;
    const int bCh = tid & 3;

    const int aLRow = lane & 15;
    const int aLW   = (lane & 16) ? 4 : 0;
    const int bLRow = ((lane & 16) ? 8 : 0) + (lane & 7);
    const int bLW   = (lane & 8) ? 4 : 0;

    float c[MI][NI][4];
    #pragma unroll
    for (int mi = 0; mi < MI; mi++)
        #pragma unroll
        for (int ni = 0; ni < NI; ni++)
            #pragma unroll
            for (int r = 0; r < 4; r++) c[mi][ni][r] = 0.f;

    const int nkb = K / GBKH;

    // prologue: stage 0 (A and B both via cp.async)
    #pragma unroll
    for (int i = 0; i < AIT; i++) {
        const int cc = tid + i * 256;
        const int row = cc >> 2, ch = cc & 3;
        cpasync16(&As[0][row * AS_W + ch * 4],
                  A + (size_t)(bm + row) * K + ch * 8);
    }
    cpasync16(&Bs[0][bN * BS_W + bCh * 4],
              Wt + (size_t)(bn + bN) * K + bCh * 8);
    cpasync_commit();

    for (int kb = 0; kb < nkb; kb++) {
        const int cur = kb & 1;
        if (kb + 1 < nkb) {
            const int nxt = cur ^ 1;
            const int k0 = (kb + 1) * GBKH;
            #pragma unroll
            for (int i = 0; i < AIT; i++) {
                const int cc = tid + i * 256;
                const int row = cc >> 2, ch = cc & 3;
                cpasync16(&As[nxt][row * AS_W + ch * 4],
                          A + (size_t)(bm + row) * K + k0 + ch * 8);
            }
            cpasync16(&Bs[nxt][bN * BS_W + bCh * 4],
                      Wt + (size_t)(bn + bN) * K + k0 + bCh * 8);
            cpasync_commit();
            cpasync_wait<1>();
        } else {
            cpasync_wait<0>();
        }
        __syncthreads();

        const uint32_t* as = As[cur];
        const uint32_t* bs = Bs[cur];
        #pragma unroll
        for (int kw = 0; kw < 16; kw += 8) {
            uint32_t af[MI][4], bf[NI][2];
            #pragma unroll
            for (int mi = 0; mi < MI; mi++)
                ldsm_x4(af[mi], &as[(warpM + mi * 16 + aLRow) * AS_W + kw + aLW]);
            #pragma unroll
            for (int np = 0; np < NI / 2; np++)
                ldsm_x4(&bf[np * 2][0],
                        &bs[(warpN + np * 16 + bLRow) * BS_W + kw + bLW]);
            #pragma unroll
            for (int mi = 0; mi < MI; mi++)
                #pragma unroll
                for (int ni = 0; ni < NI; ni++)
                    mma_f16(c[mi][ni], af[mi], bf[ni]);
        }
        __syncthreads();
    }

    #pragma unroll
    for (int mi = 0; mi < MI; mi++) {
        #pragma unroll
        for (int ni = 0; ni < NI; ni++) {
            const int col = bn + warpN + ni * 8 + tg * 2;
            const float b0 = bias[col], b1 = bias[col + 1];
            #pragma unroll
            for (int h = 0; h < 2; h++) {
                const int row = bm + warpM + mi * 16 + g + h * 8;
                float v0 = c[mi][ni][2 * h + 0] + b0;
                float v1 = c[mi][ni][2 * h + 1] + b1;
                if (ep == EP_RES) {
                    const float2 rr = *(const float2*)(R + (size_t)row * N + col);
                    v0 += rr.x; v1 += rr.y;
                    *(float2*)(Cf + (size_t)row * N + col) = make_float2(v0, v1);
                } else {
                    if (ep == EP_GELU) {
                        v0 = 0.5f * v0 * (1.0f + erff(v0 * 0.70710678118654752f));
                        v1 = 0.5f * v1 * (1.0f + erff(v1 * 0.70710678118654752f));
                    }
                    *(uint32_t*)(Ch + (size_t)row * N + col) = packh2(v0, v1);
                }
            }
        }
    }
}

__global__ __launch_bounds__(256) void hgemm_ep128(
    const __half* __restrict__ A, const __half* __restrict__ Wt,
    const float* __restrict__ bias, const float* __restrict__ R,
    float* __restrict__ Cf, __half* __restrict__ Ch,
    int M, int N, int K, int ep)
{
    hgemm_body<128>(A, Wt, bias, R, Cf, Ch, M, N, K, ep,
                    blockIdx.y * 128, blockIdx.x * GBN);
}

__global__ __launch_bounds__(256) void hgemm_ep64(
    const __half* __restrict__ A, const __half* __restrict__ Wt,
    const float* __restrict__ bias, const float* __restrict__ R,
    float* __restrict__ Cf, __half* __restrict__ Ch,
    int M, int N, int K, int ep)
{
    hgemm_body<64>(A, Wt, bias, R, Cf, Ch, M, N, K, ep,
                   blockIdx.y * 64, blockIdx.x * GBN);
}

__global__ __launch_bounds__(256) void hgemm_qkv(
    const __half* __restrict__ Aq, const __half* __restrict__ Akv,
    const __half* __restrict__ Wq, const float* __restrict__ bq,
    const __half* __restrict__ Wk, const float* __restrict__ bk,
    const __half* __restrict__ Wv, const float* __restrict__ bv,
    __half* __restrict__ Cq, __half* __restrict__ Ck, __half* __restrict__ Cv)
{
    const int z = blockIdx.z;
    const __half* A = (z == 0) ? Aq : Akv;
    const __half* W = (z == 0) ? Wq : (z == 1) ? Wk : Wv;
    const float* bia = (z == 0) ? bq : (z == 1) ? bk : bv;
    __half* C = (z == 0) ? Cq : (z == 1) ? Ck : Cv;
    hgemm_body<128>(A, W, bia, nullptr, nullptr, C, ROWS, EMBED, EMBED, EP_BIAS,
                    blockIdx.y * 128, blockIdx.x * GBN);
}

// ================= fp16 flash attention (fp16 in / fp16 out) ================
#define ATQ 64
#define ATK 64
#define KQ_W 36
#define V_W  72

__global__ __launch_bounds__(128) void flash_f16(
    const __half* __restrict__ Qh, const __half* __restrict__ Kh,
    const __half* __restrict__ Vh, __half* __restrict__ Oh, int causal)
{
    __shared__ uint32_t Qs[ATQ * KQ_W];
    __shared__ uint32_t Ks[ATK * KQ_W];
    __shared__ uint32_t Vs[(ATK / 2) * V_W];

    const int b = blockIdx.z, h = blockIdx.y, qb = blockIdx.x;
    const int tid = threadIdx.x;
    const int wid = tid >> 5, lane = tid & 31;
    const int g = lane >> 2, tg = lane & 3;
    const int qbase = qb * ATQ;
    const int m0 = wid * 16;

    const int kLRow = ((lane & 16) ? 8 : 0) + (lane & 7);
    const int kLW   = (lane & 8) ? 4 : 0;

    // ---- Q tile: fp16 load, scale by 1/8 in half (exact, power of 2) ----
    const half2 s2 = __floats2half2_rn(0.125f, 0.125f);
    #pragma unroll
    for (int i = 0; i < 4; i++) {
        const int idx = tid + i * 128;
        const int r = idx >> 3;
        const int c8 = (idx & 7) * 8;     // half offset
        uint4 qw = *(const uint4*)(Qh + ((size_t)(b * SEQ + qbase + r)) * EMBED + h * DH + c8);
        qw.x = hmul2_u(qw.x, s2);
        qw.y = hmul2_u(qw.y, s2);
        qw.z = hmul2_u(qw.z, s2);
        qw.w = hmul2_u(qw.w, s2);
        *(uint4*)(&Qs[r * KQ_W + (idx & 7) * 4]) = qw;
    }
    __syncthreads();

    uint32_t qf[4][4];
    #pragma unroll
    for (int s = 0; s < 4; s++) {
        qf[s][0] = Qs[(m0 + g    ) * KQ_W + 8 * s + tg    ];
        qf[s][1] = Qs[(m0 + g + 8) * KQ_W + 8 * s + tg    ];
        qf[s][2] = Qs[(m0 + g    ) * KQ_W + 8 * s + tg + 4];
        qf[s][3] = Qs[(m0 + g + 8) * KQ_W + 8 * s + tg + 4];
    }

    float oacc[8][4];
    #pragma unroll
    for (int ni = 0; ni < 8; ni++)
        #pragma unroll
        for (int r = 0; r < 4; r++) oacc[ni][r] = 0.f;
    float m0r = -1e30f, m1r = -1e30f, l0r = 0.f, l1r = 0.f;

    const int nkt = causal ? (qb + 1) : (SEQ / ATK);
    for (int kt = 0; kt < nkt; kt++) {
        // ---- K tile via cp.async (fp16 natural layout) ----
        #pragma unroll
        for (int i = 0; i < 4; i++) {
            const int idx = tid + i * 128;
            const int r = idx >> 3;
            const int ch = idx & 7;
            cpasync16(&Ks[r * KQ_W + ch * 4],
                      Kh + ((size_t)(b * SEQ + kt * ATK + r)) * EMBED + h * DH + ch * 8);
        }
        cpasync_commit();
        // ---- V tile: fp16 loads, byte_perm key-pair interleave ----
        #pragma unroll
        for (int i = 0; i < 2; i++) {
            const int u = tid + i * 128;
            const int kp = u >> 3;
            const int d8 = (u & 7) * 8;
            const size_t go = ((size_t)(b * SEQ + kt * ATK + 2 * kp)) * EMBED + h * DH + d8;
            uint4 a = *(const uint4*)(Vh + go);
            uint4 bb = *(const uint4*)(Vh + go + EMBED);
            uint4 o0, o1;
            o0.x = __byte_perm(a.x, bb.x, 0x5410);
            o0.y = __byte_perm(a.x, bb.x, 0x7632);
            o0.z = __byte_perm(a.y, bb.y, 0x5410);
            o0.w = __byte_perm(a.y, bb.y, 0x7632);
            o1.x = __byte_perm(a.z, bb.z, 0x5410);
            o1.y = __byte_perm(a.z, bb.z, 0x7632);
            o1.z = __byte_perm(a.w, bb.w, 0x5410);
            o1.w = __byte_perm(a.w, bb.w, 0x7632);
            *(uint4*)(&Vs[kp * V_W + d8])     = o0;
            *(uint4*)(&Vs[kp * V_W + d8 + 4]) = o1;
        }
        cpasync_wait<0>();
        __syncthreads();

        // ---- S = Q K^T ----
        float sacc[8][4];
        #pragma unroll
        for (int ni = 0; ni < 8; ni++)
            #pragma unroll
            for (int r = 0; r < 4; r++) sacc[ni][r] = 0.f;
        #pragma unroll
        for (int s = 0; s < 4; s++) {
            uint32_t kf[8][2];
            #pragma unroll
            for (int np = 0; np < 4; np++)
                ldsm_x4(&kf[np * 2][0],
                        &Ks[(np * 16 + kLRow) * KQ_W + 8 * s + kLW]);
            #pragma unroll
            for (int ni = 0; ni < 8; ni++)
                mma_f16(sacc[ni], qf[s], kf[ni]);
        }

        if (causal && kt == qb) {
            const int r0 = qbase + m0 + g, r1 = r0 + 8;
            #pragma unroll
            for (int ni = 0; ni < 8; ni++) {
                const int c0 = kt * ATK + ni * 8 + 2 * tg;
                if (c0     > r0) sacc[ni][0] = -1e30f;
                if (c0 + 1 > r0) sacc[ni][1] = -1e30f;
                if (c0     > r1) sacc[ni][2] = -1e30f;
                if (c0 + 1 > r1) sacc[ni][3] = -1e30f;
            }
        }

        float mx0 = -1e30f, mx1 = -1e30f;
        #pragma unroll
        for (int ni = 0; ni < 8; ni++) {
            mx0 = fmaxf(mx0, fmaxf(sacc[ni][0], sacc[ni][1]));
            mx1 = fmaxf(mx1, fmaxf(sacc[ni][2], sacc[ni][3]));
        }
        mx0 = fmaxf(mx0, __shfl_xor_sync(0xffffffffu, mx0, 1));
        mx0 = fmaxf(mx0, __shfl_xor_sync(0xffffffffu, mx0, 2));
        mx1 = fmaxf(mx1, __shfl_xor_sync(0xffffffffu, mx1, 1));
        mx1 = fmaxf(mx1, __shfl_xor_sync(0xffffffffu, mx1, 2));
        const float mn0 = fmaxf(m0r, mx0);
        const float mn1 = fmaxf(m1r, mx1);
        const float cr0 = __expf(m0r - mn0);
        const float cr1 = __expf(m1r - mn1);
        m0r = mn0; m1r = mn1;

        uint32_t pf[8][2];
        float ls0 = 0.f, ls1 = 0.f;
        #pragma unroll
        for (int ni = 0; ni < 8; ni++) {
            const float p0 = __expf(sacc[ni][0] - mn0);
            const float p1 = __expf(sacc[ni][1] - mn0);
            const float p2 = __expf(sacc[ni][2] - mn1);
            const float p3 = __expf(sacc[ni][3] - mn1);
            ls0 += p0 + p1; ls1 += p2 + p3;
            pf[ni][0] = packh2(p0, p1);
            pf[ni][1] = packh2(p2, p3);
        }
        ls0 += __shfl_xor_sync(0xffffffffu, ls0, 1);
        ls0 += __shfl_xor_sync(0xffffffffu, ls0, 2);
        ls1 += __shfl_xor_sync(0xffffffffu, ls1, 1);
        ls1 += __shfl_xor_sync(0xffffffffu, ls1, 2);
        l0r = l0r * cr0 + ls0;
        l1r = l1r * cr1 + ls1;

        #pragma unroll
        for (int ni = 0; ni < 8; ni++) {
            oacc[ni][0] *= cr0; oacc[ni][1] *= cr0;
            oacc[ni][2] *= cr1; oacc[ni][3] *= cr1;
        }

        #pragma unroll
        for (int s = 0; s < 4; s++) {
            uint32_t af[4];
            af[0] = pf[2 * s    ][0];
            af[1] = pf[2 * s    ][1];
            af[2] = pf[2 * s + 1][0];
            af[3] = pf[2 * s + 1][1];
            #pragma unroll
            for (int ni = 0; ni < 8; ni++) {
                uint32_t bf[2];
                bf[0] = Vs[(8 * s + tg    ) * V_W + ni * 8 + g];
                bf[1] = Vs[(8 * s + tg + 4) * V_W + ni * 8 + g];
                mma_f16(oacc[ni], af, bf);
            }
        }
        __syncthreads();
    }

    const float inv0 = 1.f / l0r, inv1 = 1.f / l1r;
    #pragma unroll
    for (int ni = 0; ni < 8; ni++) {
        const size_t o0 = ((size_t)(b * SEQ + qbase + m0 + g)) * EMBED + h * DH + ni * 8 + 2 * tg;
        *(uint32_t*)(Oh + o0)             = packh2(oacc[ni][0] * inv0, oacc[ni][1] * inv0);
        *(uint32_t*)(Oh + o0 + 8 * EMBED) = packh2(oacc[ni][2] * inv1, oacc[ni][3] * inv1);
    }
}

// ---------------- LayerNorm: fp32 out + optional fp16 mirror ----------------
__global__ __launch_bounds__(128) void layernorm_k(
    const float* __restrict__ X, const float* __restrict__ G,
    const float* __restrict__ Bt, float* __restrict__ Y,
    __half* __restrict__ Yh)
{
    const int row = blockIdx.x;
    const int t = threadIdx.x;
    const float* xr = X + (size_t)row * EMBED;
    float4 v = *(const float4*)(xr + t * 4);
    float s  = v.x + v.y + v.z + v.w;
    float ss = v.x * v.x + v.y * v.y + v.z * v.z + v.w * v.w;
    #pragma unroll
    for (int o = 16; o > 0; o >>= 1) {
        s  += __shfl_xor_sync(0xffffffffu, s,  o);
        ss += __shfl_xor_sync(0xffffffffu, ss, o);
    }
    __shared__ float sh_s[4], sh_ss[4];
    const int w = t >> 5;
    if ((t & 31) == 0) { sh_s[w] = s; sh_ss[w] = ss; }
    __syncthreads();
    s  = sh_s[0] + sh_s[1] + sh_s[2] + sh_s[3];
    ss = sh_ss[0] + sh_ss[1] + sh_ss[2] + sh_ss[3];
    const float mean = s * (1.f / EMBED);
    const float var  = ss * (1.f / EMBED) - mean * mean;
    const float rstd = rsqrtf(var + 1e-5f);
    float4 gg = *(const float4*)(G  + t * 4);
    float4 bb = *(const float4*)(Bt + t * 4);
    float4 o;
    o.x = (v.x - mean) * rstd * gg.x + bb.x;
    o.y = (v.y - mean) * rstd * gg.y + bb.y;
    o.z = (v.z - mean) * rstd * gg.z + bb.z;
    o.w = (v.w - mean) * rstd * gg.w + bb.w;
    *(float4*)(Y + (size_t)row * EMBED + t * 4) = o;
    if (Yh) {
        uint2 ho = make_uint2(packh2(o.x, o.y), packh2(o.z, o.w));
        *(uint2*)(Yh + (size_t)row * EMBED + t * 4) = ho;
    }
}

// ---------------- launch --------------------------------------------------
extern "C" void kernel_launch(void* const* d_in, const int* in_sizes, int n_in,
                              void* d_out, int out_size)
{
    const float* x     = (const float*)d_in[0];
    const float* enc   = (const float*)d_in[1];
    const float* sa_wq = (const float*)d_in[2];
    const float* sa_bq = (const float*)d_in[3];
    const float* sa_wk = (const float*)d_in[4];
    const float* sa_bk = (const float*)d_in[5];
    const float* sa_wv = (const float*)d_in[6];
    const float* sa_bv = (const float*)d_in[7];
    const float* sa_wo = (const float*)d_in[8];
    const float* sa_bo = (const float*)d_in[9];
    const float* ca_wq = (const float*)d_in[10];
    const float* ca_bq = (const float*)d_in[11];
    const float* ca_wk = (const float*)d_in[12];
    const float* ca_bk = (const float*)d_in[13];
    const float* ca_wv = (const float*)d_in[14];
    const float* ca_bv = (const float*)d_in[15];
    const float* ca_wo = (const float*)d_in[16];
    const float* ca_bo = (const float*)d_in[17];
    const float* ln1_g = (const float*)d_in[18];
    const float* ln1_b = (const float*)d_in[19];
    const float* ln2_g = (const float*)d_in[20];
    const float* ln2_b = (const float*)d_in[21];
    const float* ln3_g = (const float*)d_in[22];
    const float* ln3_b = (const float*)d_in[23];
    const float* ff_w1 = (const float*)d_in[24];
    const float* ff_b1 = (const float*)d_in[25];
    const float* ff_w2 = (const float*)d_in[26];
    const float* ff_b2 = (const float*)d_in[27];
    float* out = (float*)d_out;

    float* xb;
    __half *xh, *ench, *qh, *kh, *vh, *attnh, *xbh, *hh, *wh;
    cudaGetSymbolAddress((void**)&xb,    g_x);
    cudaGetSymbolAddress((void**)&xh,    g_xh);
    cudaGetSymbolAddress((void**)&ench,  g_ench);
    cudaGetSymbolAddress((void**)&qh,    g_qh);
    cudaGetSymbolAddress((void**)&kh,    g_kh);
    cudaGetSymbolAddress((void**)&vh,    g_vh);
    cudaGetSymbolAddress((void**)&attnh, g_attnh);
    cudaGetSymbolAddress((void**)&xbh,   g_xbh);
    cudaGetSymbolAddress((void**)&hh,    g_hh);
    cudaGetSymbolAddress((void**)&wh,    g_wh);

    __half* w_saq = wh + 0 * WSQ;
    __half* w_sak = wh + 1 * WSQ;
    __half* w_sav = wh + 2 * WSQ;
    __half* w_sao = wh + 3 * WSQ;
    __half* w_caq = wh + 4 * WSQ;
    __half* w_cak = wh + 5 * WSQ;
    __half* w_cav = wh + 6 * WSQ;
    __half* w_cao = wh + 7 * WSQ;
    __half* w_ff1 = wh + 8 * WSQ;
    __half* w_ff2 = wh + 8 * WSQ + WFF;

    wconv_all<<<4096, 256>>>(sa_wq, sa_wk, sa_wv, sa_wo,
                             ca_wq, ca_wk, ca_wv, ca_wo,
                             ff_w1, ff_w2, wh);
    xconv<<<dim3(ROWS * EMBED / 4 / 256, 2), 256>>>(x, enc, xh, ench);

    dim3 g64 (EMBED / GBN, ROWS / 64);       // (8, 64)
    dim3 gqkv(EMBED / GBN, ROWS / 128, 3);   // (8, 32, 3)
    dim3 gff (FF    / GBN, ROWS / 128);      // (32, 32)
    dim3 gfl (SEQ / ATQ, NH, BATCH);         // (32, 8, 2)

    // ---- self attention (causal) ----
    hgemm_qkv<<<gqkv, 256>>>(xh, xh, w_saq, sa_bq, w_sak, sa_bk, w_sav, sa_bv,
                             qh, kh, vh);
    flash_f16<<<gfl, 128>>>(qh, kh, vh, attnh, 1);
    hgemm_ep64<<<g64, 256>>>(attnh, w_sao, sa_bo, x, xb, nullptr,
                             ROWS, EMBED, EMBED, EP_RES);
    layernorm_k<<<ROWS, 128>>>(xb, ln1_g, ln1_b, xb, xbh);

    // ---- cross attention ----
    hgemm_qkv<<<gqkv, 256>>>(xbh, ench, w_caq, ca_bq, w_cak, ca_bk, w_cav, ca_bv,
                             qh, kh, vh);
    flash_f16<<<gfl, 128>>>(qh, kh, vh, attnh, 0);
    hgemm_ep64<<<g64, 256>>>(attnh, w_cao, ca_bo, xb, xb, nullptr,
                             ROWS, EMBED, EMBED, EP_RES);
    layernorm_k<<<ROWS, 128>>>(xb, ln2_g, ln2_b, xb, xbh);

    // ---- feed-forward ----
    hgemm_ep128<<<gff, 256>>>(xbh, w_ff1, ff_b1, nullptr, nullptr, hh,
                              ROWS, FF, EMBED, EP_GELU);
    hgemm_ep64<<<g64, 256>>>(hh, w_ff2, ff_b2, xb, xb, nullptr,
                             ROWS, EMBED, FF, EP_RES);
    layernorm_k<<<ROWS, 128>>>(xb, ln3_g, ln3_b, out, nullptr);
}